// round 1
// baseline (speedup 1.0000x reference)
#include <cuda_runtime.h>
#include <cuda_bf16.h>
#include <stdint.h>

#define T_TOKENS 8192
#define DM 1024
#define DF 4096
#define NE 8
#define PAIRS 16384
#define MAXTILES 144   // worst case sum ceil(c_e/128) <= 128 + 8 = 136

// ---------------- scratch (device globals; no allocations) ----------------
__device__ __nv_bfloat16 g_xh[(size_t)T_TOKENS * DM];
__device__ __nv_bfloat16 g_xl[(size_t)T_TOKENS * DM];
__device__ __nv_bfloat16 g_Hh[(size_t)PAIRS * DF];
__device__ __nv_bfloat16 g_Hl[(size_t)PAIRS * DF];
__device__ float         g_Y[(size_t)PAIRS * DM];

__device__ int   g_pair_e[PAIRS];
__device__ float g_pair_w[PAIRS];
__device__ int   g_pair_slot[PAIRS];
__device__ int   g_rows_token[PAIRS];

__device__ int g_counts[NE];
__device__ int g_cursor[NE];
__device__ int g_off[NE + 1];
__device__ int g_tile_e[MAXTILES];
__device__ int g_tile_r0[MAXTILES];
__device__ int g_tile_valid[MAXTILES];
__device__ int g_num_tiles;

// ---------------- helpers ----------------
__device__ __forceinline__ uint32_t smaddr(const void* p) {
    return (uint32_t)__cvta_generic_to_shared(p);
}
__device__ __forceinline__ uint32_t pack_bf16(__nv_bfloat16 a, __nv_bfloat16 b) {
    return (uint32_t)__bfloat16_as_ushort(a) | ((uint32_t)__bfloat16_as_ushort(b) << 16);
}
__device__ __forceinline__ void ldsm4(uint32_t* r, uint32_t addr) {
    asm volatile("ldmatrix.sync.aligned.m8n8.x4.shared.b16 {%0,%1,%2,%3}, [%4];\n"
                 : "=r"(r[0]), "=r"(r[1]), "=r"(r[2]), "=r"(r[3]) : "r"(addr));
}
__device__ __forceinline__ void ldsm4t(uint32_t* r, uint32_t addr) {
    asm volatile("ldmatrix.sync.aligned.m8n8.x4.trans.shared.b16 {%0,%1,%2,%3}, [%4];\n"
                 : "=r"(r[0]), "=r"(r[1]), "=r"(r[2]), "=r"(r[3]) : "r"(addr));
}
__device__ __forceinline__ void mma16816(float* c, const uint32_t* a, const uint32_t* b) {
    asm volatile(
        "mma.sync.aligned.m16n8k16.row.col.f32.bf16.bf16.f32 "
        "{%0,%1,%2,%3}, {%4,%5,%6,%7}, {%8,%9}, {%0,%1,%2,%3};\n"
        : "+f"(c[0]), "+f"(c[1]), "+f"(c[2]), "+f"(c[3])
        : "r"(a[0]), "r"(a[1]), "r"(a[2]), "r"(a[3]), "r"(b[0]), "r"(b[1]));
}
__device__ __forceinline__ float gelu_exact(float v) {
    return 0.5f * v * (1.0f + erff(v * 0.70710678118654752f));
}

// ---------------- kernel 1: zero counters ----------------
__global__ void zero_kernel() {
    int t = threadIdx.x;
    if (t < NE) { g_counts[t] = 0; g_cursor[t] = 0; }
}

// ---------------- kernel 2: gating + x -> bf16 hi/lo ----------------
__global__ __launch_bounds__(256) void gate_kernel(const float* __restrict__ x,
                                                   const float* __restrict__ gw) {
    const int tk = blockIdx.x;
    const int tid = threadIdx.x;
    const float* xr = x + (size_t)tk * DM;

    float p[NE];
#pragma unroll
    for (int e = 0; e < NE; ++e) p[e] = 0.f;
    float xv[4];
#pragma unroll
    for (int j = 0; j < 4; ++j) {
        int i = j * 256 + tid;
        float v = xr[i];
        xv[j] = v;
#pragma unroll
        for (int e = 0; e < NE; ++e) p[e] += v * gw[e * DM + i];
    }
#pragma unroll
    for (int j = 0; j < 4; ++j) {
        int i = j * 256 + tid;
        __nv_bfloat16 h = __float2bfloat16_rn(xv[j]);
        g_xh[(size_t)tk * DM + i] = h;
        g_xl[(size_t)tk * DM + i] = __float2bfloat16_rn(xv[j] - __bfloat162float(h));
    }
#pragma unroll
    for (int e = 0; e < NE; ++e)
#pragma unroll
        for (int o = 16; o > 0; o >>= 1) p[e] += __shfl_xor_sync(0xffffffffu, p[e], o);

    __shared__ float sRed[8][NE];
    int lane = tid & 31, w = tid >> 5;
    if (lane == 0) {
#pragma unroll
        for (int e = 0; e < NE; ++e) sRed[w][e] = p[e];
    }
    __syncthreads();
    if (tid == 0) {
        float lg[NE];
#pragma unroll
        for (int e = 0; e < NE; ++e) {
            float s = 0.f;
#pragma unroll
            for (int ww = 0; ww < 8; ++ww) s += sRed[ww][e];
            lg[e] = s;
        }
        float m = lg[0];
#pragma unroll
        for (int e = 1; e < NE; ++e) m = fmaxf(m, lg[e]);
        float ex[NE], S = 0.f;
#pragma unroll
        for (int e = 0; e < NE; ++e) { ex[e] = expf(lg[e] - m); S += ex[e]; }
        int i0 = 0;
#pragma unroll
        for (int e = 1; e < NE; ++e) if (ex[e] > ex[i0]) i0 = e;
        int i1 = (i0 == 0) ? 1 : 0;
#pragma unroll
        for (int e = 0; e < NE; ++e) if (e != i0 && ex[e] > ex[i1]) i1 = e;
        float p0 = ex[i0] / S, p1 = ex[i1] / S;
        float den = p0 + p1 + 1e-9f;
        g_pair_e[2 * tk] = i0;     g_pair_w[2 * tk] = p0 / den;
        g_pair_e[2 * tk + 1] = i1; g_pair_w[2 * tk + 1] = p1 / den;
        atomicAdd(&g_counts[i0], 1);
        atomicAdd(&g_counts[i1], 1);
    }
}

// ---------------- kernel 3: scan + tile map ----------------
__global__ void scan_kernel() {
    if (threadIdx.x == 0) {
        int off = 0, nt = 0;
        for (int e = 0; e < NE; ++e) {
            g_off[e] = off;
            int c = g_counts[e];
            int tiles = (c + 127) >> 7;
            for (int i = 0; i < tiles; ++i) {
                g_tile_e[nt] = e;
                g_tile_r0[nt] = off + i * 128;
                int v = c - i * 128;
                g_tile_valid[nt] = v > 128 ? 128 : v;
                ++nt;
            }
            off += c;
        }
        g_off[NE] = off;
        g_num_tiles = nt;
    }
}

// ---------------- kernel 4: scatter pairs into expert segments ----------------
__global__ void scatter_kernel() {
    int p = blockIdx.x * 256 + threadIdx.x;
    if (p >= PAIRS) return;
    int e = g_pair_e[p];
    int slot = g_off[e] + atomicAdd(&g_cursor[e], 1);
    g_pair_slot[p] = slot;
    g_rows_token[slot] = p >> 1;
}

// ---------------- GEMM (templated for layer 1 / layer 2) ----------------
// BM=128, BN=128, BK=32, 8 warps (2x4), warp tile 64x32, hi/lo split (3 mma passes)
template <bool FIRST>
__global__ __launch_bounds__(256) void moe_gemm(const float* __restrict__ W,
                                                const float* __restrict__ bias) {
    constexpr int KTOT = FIRST ? DM : DF;   // 1024 : 4096
    constexpr int LDW  = FIRST ? DF : DM;   // 4096 : 1024  (also = bias width = N total)
    const int tileIdx = blockIdx.y;
    if (tileIdx >= g_num_tiles) return;
    const int e = g_tile_e[tileIdx];
    const int row0 = g_tile_r0[tileIdx];
    const int vrows = g_tile_valid[tileIdx];
    const int n0 = blockIdx.x * 128;
    const float* Wn = W + (size_t)e * KTOT * LDW + n0;
    const float* bn = bias + (size_t)e * LDW + n0;

    __shared__ __align__(16) __nv_bfloat16 sAh[128 * 40];
    __shared__ __align__(16) __nv_bfloat16 sAl[128 * 40];
    __shared__ __align__(16) __nv_bfloat16 sBh[32 * 136];
    __shared__ __align__(16) __nv_bfloat16 sBl[32 * 136];
    __shared__ int sTok[128];

    const int t = threadIdx.x;
    if (FIRST) {
        if (t < 128) {
            int r = row0 + t;
            sTok[t] = (t < vrows) ? g_rows_token[r < PAIRS ? r : PAIRS - 1] : 0;
        }
    }
    __syncthreads();

    float c[4][4][4];
#pragma unroll
    for (int a = 0; a < 4; ++a)
#pragma unroll
        for (int b = 0; b < 4; ++b)
#pragma unroll
            for (int q = 0; q < 4; ++q) c[a][b][q] = 0.f;

    const int lane = t & 31, warp = t >> 5;
    const int wm = warp >> 2, wn = warp & 3;
    const int m0 = wm * 64;
    const int sub = t & 15, rgrp = t >> 4;

    for (int k0 = 0; k0 < KTOT; k0 += 32) {
        __syncthreads();
        // --- load A tile (hi/lo bf16) ---
#pragma unroll
        for (int rr = 0; rr < 8; ++rr) {
            int r = rr * 16 + rgrp;
            const uint32_t *ph, *pl;
            if (FIRST) {
                int tok = sTok[r];
                ph = reinterpret_cast<const uint32_t*>(g_xh + (size_t)tok * DM + k0);
                pl = reinterpret_cast<const uint32_t*>(g_xl + (size_t)tok * DM + k0);
            } else {
                int rg = row0 + r; if (rg > PAIRS - 1) rg = PAIRS - 1;
                ph = reinterpret_cast<const uint32_t*>(g_Hh + (size_t)rg * DF + k0);
                pl = reinterpret_cast<const uint32_t*>(g_Hl + (size_t)rg * DF + k0);
            }
            *reinterpret_cast<uint32_t*>(&sAh[r * 40 + sub * 2]) = ph[sub];
            *reinterpret_cast<uint32_t*>(&sAl[r * 40 + sub * 2]) = pl[sub];
        }
        // --- load B tile fp32 -> split to hi/lo bf16 ---
#pragma unroll
        for (int i = 0; i < 4; ++i) {
            int lin = (i * 256 + t) * 4;
            int kr = lin >> 7;
            int nc = lin & 127;
            const float4 v = *reinterpret_cast<const float4*>(Wn + (size_t)(k0 + kr) * LDW + nc);
            __nv_bfloat16 h0 = __float2bfloat16_rn(v.x);
            __nv_bfloat16 h1 = __float2bfloat16_rn(v.y);
            __nv_bfloat16 h2 = __float2bfloat16_rn(v.z);
            __nv_bfloat16 h3 = __float2bfloat16_rn(v.w);
            __nv_bfloat16 l0 = __float2bfloat16_rn(v.x - __bfloat162float(h0));
            __nv_bfloat16 l1 = __float2bfloat16_rn(v.y - __bfloat162float(h1));
            __nv_bfloat16 l2 = __float2bfloat16_rn(v.z - __bfloat162float(h2));
            __nv_bfloat16 l3 = __float2bfloat16_rn(v.w - __bfloat162float(h3));
            *reinterpret_cast<uint2*>(&sBh[kr * 136 + nc]) = make_uint2(pack_bf16(h0, h1), pack_bf16(h2, h3));
            *reinterpret_cast<uint2*>(&sBl[kr * 136 + nc]) = make_uint2(pack_bf16(l0, l1), pack_bf16(l2, l3));
        }
        __syncthreads();

#pragma unroll
        for (int ks = 0; ks < 2; ++ks) {
            uint32_t ah[4][4], al[4][4], bh[4][2], bl[4][2];
            {
                int arow = lane & 15;
                int acol = ks * 16 + (lane >> 4) * 8;
#pragma unroll
                for (int fm = 0; fm < 4; ++fm) {
                    ldsm4(ah[fm], smaddr(&sAh[(m0 + fm * 16 + arow) * 40 + acol]));
                    ldsm4(al[fm], smaddr(&sAl[(m0 + fm * 16 + arow) * 40 + acol]));
                }
                int brow = ks * 16 + (lane & 15);
                int bcol = wn * 32 + (lane >> 4) * 8;
#pragma unroll
                for (int hb = 0; hb < 2; ++hb) {
                    uint32_t r[4];
                    ldsm4t(r, smaddr(&sBh[brow * 136 + bcol + hb * 16]));
                    bh[2 * hb][0] = r[0]; bh[2 * hb][1] = r[1];
                    bh[2 * hb + 1][0] = r[2]; bh[2 * hb + 1][1] = r[3];
                    ldsm4t(r, smaddr(&sBl[brow * 136 + bcol + hb * 16]));
                    bl[2 * hb][0] = r[0]; bl[2 * hb][1] = r[1];
                    bl[2 * hb + 1][0] = r[2]; bl[2 * hb + 1][1] = r[3];
                }
            }
#pragma unroll
            for (int fm = 0; fm < 4; ++fm)
#pragma unroll
                for (int fn = 0; fn < 4; ++fn) {
                    mma16816(c[fm][fn], ah[fm], bh[fn]);
                    mma16816(c[fm][fn], ah[fm], bl[fn]);
                    mma16816(c[fm][fn], al[fm], bh[fn]);
                }
        }
    }

    // --- epilogue ---
    const int lgrp = lane >> 2, lq = lane & 3;
#pragma unroll
    for (int fm = 0; fm < 4; ++fm) {
        int rl = m0 + fm * 16 + lgrp;
#pragma unroll
        for (int fn = 0; fn < 4; ++fn) {
            int nc = wn * 32 + fn * 8 + lq * 2;
            float bv0 = bn[nc], bv1 = bn[nc + 1];
            float* cc = c[fm][fn];
#pragma unroll
            for (int h = 0; h < 2; ++h) {
                int rloc = rl + h * 8;
                if (rloc < vrows) {
                    int row = row0 + rloc;
                    float v0 = cc[h * 2 + 0] + bv0;
                    float v1 = cc[h * 2 + 1] + bv1;
                    if (FIRST) {
                        v0 = gelu_exact(v0);
                        v1 = gelu_exact(v1);
                        __nv_bfloat16 h0 = __float2bfloat16_rn(v0);
                        __nv_bfloat16 h1 = __float2bfloat16_rn(v1);
                        *reinterpret_cast<uint32_t*>(&g_Hh[(size_t)row * DF + n0 + nc]) = pack_bf16(h0, h1);
                        __nv_bfloat16 l0 = __float2bfloat16_rn(v0 - __bfloat162float(h0));
                        __nv_bfloat16 l1 = __float2bfloat16_rn(v1 - __bfloat162float(h1));
                        *reinterpret_cast<uint32_t*>(&g_Hl[(size_t)row * DF + n0 + nc]) = pack_bf16(l0, l1);
                    } else {
                        *reinterpret_cast<float2*>(&g_Y[(size_t)row * DM + n0 + nc]) = make_float2(v0, v1);
                    }
                }
            }
        }
    }
}

// ---------------- kernel 7: weighted combine ----------------
__global__ __launch_bounds__(256) void combine_kernel(float* __restrict__ out) {
    const int tk = blockIdx.x;
    const int d = threadIdx.x * 4;
    int s0 = g_pair_slot[2 * tk], s1 = g_pair_slot[2 * tk + 1];
    float w0 = g_pair_w[2 * tk], w1 = g_pair_w[2 * tk + 1];
    const float4 a = *reinterpret_cast<const float4*>(&g_Y[(size_t)s0 * DM + d]);
    const float4 b = *reinterpret_cast<const float4*>(&g_Y[(size_t)s1 * DM + d]);
    float4 o;
    o.x = w0 * a.x + w1 * b.x;
    o.y = w0 * a.y + w1 * b.y;
    o.z = w0 * a.z + w1 * b.z;
    o.w = w0 * a.w + w1 * b.w;
    *reinterpret_cast<float4*>(&out[(size_t)tk * DM + d]) = o;
}

// ---------------- launch ----------------
extern "C" void kernel_launch(void* const* d_in, const int* in_sizes, int n_in,
                              void* d_out, int out_size) {
    const float* x  = (const float*)d_in[0];
    const float* gw = (const float*)d_in[1];
    const float* w1 = (const float*)d_in[2];
    const float* b1 = (const float*)d_in[3];
    const float* w2 = (const float*)d_in[4];
    const float* b2 = (const float*)d_in[5];
    float* out = (float*)d_out;

    zero_kernel<<<1, 32>>>();
    gate_kernel<<<T_TOKENS, 256>>>(x, gw);
    scan_kernel<<<1, 32>>>();
    scatter_kernel<<<PAIRS / 256, 256>>>();
    moe_gemm<true><<<dim3(DF / 128, 136), 256>>>(w1, b1);
    moe_gemm<false><<<dim3(DM / 128, 136), 256>>>(w2, b2);
    combine_kernel<<<T_TOKENS, 256>>>(out);
}

// round 4
// speedup vs baseline: 3.4306x; 3.4306x over previous
#include <cuda_runtime.h>
#include <cuda_bf16.h>
#include <stdint.h>

#define T_TOKENS 8192
#define DM 1024
#define DF 4096
#define NE 8
#define PAIRS 16384
#define MAXTILES 144

// tcgen05 availability: only in the arch-SPECIFIC device pass (sm_103a / sm_100a).
#if defined(__CUDA_ARCH__) && (defined(__CUDA_ARCH_FEAT_SM103_ALL) || defined(__CUDA_ARCH_FEAT_SM100_ALL) || defined(__CUDA_ARCH_SPECIFIC__))
#define HAS_TC 1
#else
#define HAS_TC 0
#endif

// ---------------- scratch (device globals; no allocations) ----------------
__device__ __align__(128) __nv_bfloat16 g_xh[(size_t)T_TOKENS * DM];
__device__ __align__(128) __nv_bfloat16 g_xl[(size_t)T_TOKENS * DM];
__device__ __align__(128) __nv_bfloat16 g_Hh[(size_t)PAIRS * DF];
__device__ __align__(128) __nv_bfloat16 g_Hl[(size_t)PAIRS * DF];
__device__ __align__(128) float         g_Y[(size_t)PAIRS * DM];

// pre-split, pre-transposed weights: [E][N][K] bf16 hi/lo (tc path only)
__device__ __align__(128) __nv_bfloat16 g_w1h[(size_t)NE * DM * DF];
__device__ __align__(128) __nv_bfloat16 g_w1l[(size_t)NE * DM * DF];
__device__ __align__(128) __nv_bfloat16 g_w2h[(size_t)NE * DF * DM];
__device__ __align__(128) __nv_bfloat16 g_w2l[(size_t)NE * DF * DM];

__device__ int   g_pair_e[PAIRS];
__device__ float g_pair_w[PAIRS];
__device__ int   g_pair_slot[PAIRS];
__device__ int   g_rows_token[PAIRS];

__device__ int g_counts[NE];
__device__ int g_cursor[NE];
__device__ int g_off[NE + 1];
__device__ int g_tile_e[MAXTILES];
__device__ int g_tile_r0[MAXTILES];
__device__ int g_tile_valid[MAXTILES];
__device__ int g_num_tiles;

// ---------------- shared helpers ----------------
__device__ __forceinline__ uint32_t smaddr(const void* p) {
    return (uint32_t)__cvta_generic_to_shared(p);
}
__device__ __forceinline__ uint32_t pack_bf16(__nv_bfloat16 a, __nv_bfloat16 b) {
    return (uint32_t)__bfloat16_as_ushort(a) | ((uint32_t)__bfloat16_as_ushort(b) << 16);
}
__device__ __forceinline__ float gelu_exact(float v) {
    return 0.5f * v * (1.0f + erff(v * 0.70710678118654752f));
}

#if HAS_TC
// ---------------- tcgen05-path helpers ----------------
__device__ __forceinline__ uint32_t elect_one() {
    uint32_t pred;
    asm volatile("{\n\t.reg .pred p;\n\telect.sync _|p, 0xFFFFFFFF;\n\tselp.b32 %0, 1, 0, p;\n\t}"
                 : "=r"(pred));
    return pred;
}
__device__ __forceinline__ void cpa16(uint32_t dst, const void* src) {
    asm volatile("cp.async.cg.shared.global [%0], [%1], 16;\n" :: "r"(dst), "l"(src));
}
__device__ __forceinline__ void cpa_commit() {
    asm volatile("cp.async.commit_group;\n" ::: "memory");
}
__device__ __forceinline__ void cpa_wait0() {
    asm volatile("cp.async.wait_group 0;\n" ::: "memory");
}
__device__ __forceinline__ void fence_async_smem() {
    asm volatile("fence.proxy.async.shared::cta;" ::: "memory");
}
__device__ __forceinline__ void mbar_init(uint32_t addr, uint32_t cnt) {
    asm volatile("mbarrier.init.shared.b64 [%0], %1;" :: "r"(addr), "r"(cnt) : "memory");
}
__device__ __forceinline__ void mbar_inval(uint32_t addr) {
    asm volatile("mbarrier.inval.shared.b64 [%0];" :: "r"(addr) : "memory");
}
__device__ __forceinline__ void mbar_wait(uint32_t addr, uint32_t parity) {
    asm volatile(
        "{\n\t.reg .pred P1;\n"
        "WAIT_%=:\n\t"
        "mbarrier.try_wait.parity.acquire.cta.shared::cta.b64 P1, [%0], %1, 0x989680;\n\t"
        "@P1 bra.uni DONE_%=;\n\t"
        "bra.uni WAIT_%=;\n"
        "DONE_%=:\n\t}"
        :: "r"(addr), "r"(parity) : "memory");
}
__device__ __forceinline__ void tc_mma_f16_ss(uint32_t d, uint64_t a, uint64_t b,
                                              uint32_t idesc, uint32_t en) {
    asm volatile(
        "{\n\t.reg .pred p;\n\tsetp.ne.u32 p, %5, 0;\n\t"
        "tcgen05.mma.cta_group::1.kind::f16 [%0], %1, %2, %3, {%4, %4, %4, %4}, p;\n\t}"
        :: "r"(d), "l"(a), "l"(b), "r"(idesc), "r"(0u), "r"(en) : "memory");
}
__device__ __forceinline__ void tc_commit(uint32_t mbar) {
    asm volatile("tcgen05.commit.cta_group::1.mbarrier::arrive::one.shared::cluster.b64 [%0];"
                 :: "r"(mbar) : "memory");
}
__device__ __forceinline__ void tc_alloc(uint32_t smem_slot, uint32_t ncols) {
    asm volatile("tcgen05.alloc.cta_group::1.sync.aligned.shared::cta.b32 [%0], %1;"
                 :: "r"(smem_slot), "r"(ncols) : "memory");
}
__device__ __forceinline__ void tc_dealloc(uint32_t tmem, uint32_t ncols) {
    asm volatile("tcgen05.dealloc.cta_group::1.sync.aligned.b32 %0, %1;" :: "r"(tmem), "r"(ncols));
}
__device__ __forceinline__ void tc_relinq() {
    asm volatile("tcgen05.relinquish_alloc_permit.cta_group::1.sync.aligned;");
}
__device__ __forceinline__ void tc_fence_after() {
    asm volatile("tcgen05.fence::after_thread_sync;" ::: "memory");
}
__device__ __forceinline__ void tc_wait_ld() {
    asm volatile("tcgen05.wait::ld.sync.aligned;" ::: "memory");
}
__device__ __forceinline__ void tc_ld_x32(uint32_t* r, uint32_t addr) {
    asm volatile(
        "tcgen05.ld.sync.aligned.32x32b.x32.b32 "
        "{%0, %1, %2, %3, %4, %5, %6, %7, %8, %9, %10, %11, %12, %13, %14, %15, "
        " %16, %17, %18, %19, %20, %21, %22, %23, %24, %25, %26, %27, %28, %29, %30, %31}, [%32];"
        : "=r"(r[0]), "=r"(r[1]), "=r"(r[2]), "=r"(r[3]), "=r"(r[4]), "=r"(r[5]), "=r"(r[6]), "=r"(r[7]),
          "=r"(r[8]), "=r"(r[9]), "=r"(r[10]), "=r"(r[11]), "=r"(r[12]), "=r"(r[13]), "=r"(r[14]), "=r"(r[15]),
          "=r"(r[16]), "=r"(r[17]), "=r"(r[18]), "=r"(r[19]), "=r"(r[20]), "=r"(r[21]), "=r"(r[22]), "=r"(r[23]),
          "=r"(r[24]), "=r"(r[25]), "=r"(r[26]), "=r"(r[27]), "=r"(r[28]), "=r"(r[29]), "=r"(r[30]), "=r"(r[31])
        : "r"(addr));
}
// SW128 K-major descriptor base (LBO=1, SBO=64, version=1, layout SW128)
__device__ __forceinline__ uint64_t mk_desc(uint32_t addr) {
    const uint64_t DBASE = (2ULL << 61) | (1ULL << 46) | (64ULL << 32) | (1ULL << 16);
    return DBASE | (uint64_t)((addr >> 4) & 0x3FFF);
}
#endif  // HAS_TC

#if !HAS_TC
// ---------------- fallback-path helpers (mma.sync) ----------------
__device__ __forceinline__ void ldsm4(uint32_t* r, uint32_t addr) {
    asm volatile("ldmatrix.sync.aligned.m8n8.x4.shared.b16 {%0,%1,%2,%3}, [%4];\n"
                 : "=r"(r[0]), "=r"(r[1]), "=r"(r[2]), "=r"(r[3]) : "r"(addr));
}
__device__ __forceinline__ void ldsm4t(uint32_t* r, uint32_t addr) {
    asm volatile("ldmatrix.sync.aligned.m8n8.x4.trans.shared.b16 {%0,%1,%2,%3}, [%4];\n"
                 : "=r"(r[0]), "=r"(r[1]), "=r"(r[2]), "=r"(r[3]) : "r"(addr));
}
__device__ __forceinline__ void mma16816(float* c, const uint32_t* a, const uint32_t* b) {
    asm volatile(
        "mma.sync.aligned.m16n8k16.row.col.f32.bf16.bf16.f32 "
        "{%0,%1,%2,%3}, {%4,%5,%6,%7}, {%8,%9}, {%0,%1,%2,%3};\n"
        : "+f"(c[0]), "+f"(c[1]), "+f"(c[2]), "+f"(c[3])
        : "r"(a[0]), "r"(a[1]), "r"(a[2]), "r"(a[3]), "r"(b[0]), "r"(b[1]));
}
#endif  // !HAS_TC

// ---------------- kernel: zero counters ----------------
__global__ void zero_kernel() {
    int t = threadIdx.x;
    if (t < NE) { g_counts[t] = 0; g_cursor[t] = 0; }
}

// ---------------- kernel: gating + x -> bf16 hi/lo ----------------
__global__ __launch_bounds__(256) void gate_kernel(const float* __restrict__ x,
                                                   const float* __restrict__ gw) {
    const int tk = blockIdx.x;
    const int tid = threadIdx.x;
    const float* xr = x + (size_t)tk * DM;

    float p[NE];
#pragma unroll
    for (int e = 0; e < NE; ++e) p[e] = 0.f;
    float xv[4];
#pragma unroll
    for (int j = 0; j < 4; ++j) {
        int i = j * 256 + tid;
        float v = xr[i];
        xv[j] = v;
#pragma unroll
        for (int e = 0; e < NE; ++e) p[e] += v * gw[e * DM + i];
    }
#pragma unroll
    for (int j = 0; j < 4; ++j) {
        int i = j * 256 + tid;
        __nv_bfloat16 h = __float2bfloat16_rn(xv[j]);
        g_xh[(size_t)tk * DM + i] = h;
        g_xl[(size_t)tk * DM + i] = __float2bfloat16_rn(xv[j] - __bfloat162float(h));
    }
#pragma unroll
    for (int e = 0; e < NE; ++e)
#pragma unroll
        for (int o = 16; o > 0; o >>= 1) p[e] += __shfl_xor_sync(0xffffffffu, p[e], o);

    __shared__ float sRed[8][NE];
    int lane = tid & 31, w = tid >> 5;
    if (lane == 0) {
#pragma unroll
        for (int e = 0; e < NE; ++e) sRed[w][e] = p[e];
    }
    __syncthreads();
    if (tid == 0) {
        float lg[NE];
#pragma unroll
        for (int e = 0; e < NE; ++e) {
            float s = 0.f;
#pragma unroll
            for (int ww = 0; ww < 8; ++ww) s += sRed[ww][e];
            lg[e] = s;
        }
        float m = lg[0];
#pragma unroll
        for (int e = 1; e < NE; ++e) m = fmaxf(m, lg[e]);
        float ex[NE], S = 0.f;
#pragma unroll
        for (int e = 0; e < NE; ++e) { ex[e] = expf(lg[e] - m); S += ex[e]; }
        int i0 = 0;
#pragma unroll
        for (int e = 1; e < NE; ++e) if (ex[e] > ex[i0]) i0 = e;
        int i1 = (i0 == 0) ? 1 : 0;
#pragma unroll
        for (int e = 0; e < NE; ++e) if (e != i0 && ex[e] > ex[i1]) i1 = e;
        float p0 = ex[i0] / S, p1 = ex[i1] / S;
        float den = p0 + p1 + 1e-9f;
        g_pair_e[2 * tk] = i0;     g_pair_w[2 * tk] = p0 / den;
        g_pair_e[2 * tk + 1] = i1; g_pair_w[2 * tk + 1] = p1 / den;
        atomicAdd(&g_counts[i0], 1);
        atomicAdd(&g_counts[i1], 1);
    }
}

// ---------------- kernel: scan + tile map ----------------
__global__ void scan_kernel() {
    if (threadIdx.x == 0) {
        int off = 0, nt = 0;
        for (int e = 0; e < NE; ++e) {
            g_off[e] = off;
            int c = g_counts[e];
            int tiles = (c + 127) >> 7;
            for (int i = 0; i < tiles; ++i) {
                g_tile_e[nt] = e;
                g_tile_r0[nt] = off + i * 128;
                int v = c - i * 128;
                g_tile_valid[nt] = v > 128 ? 128 : v;
                ++nt;
            }
            off += c;
        }
        g_off[NE] = off;
        g_num_tiles = nt;
    }
}

// ---------------- kernel: scatter pairs into expert segments ----------------
__global__ void scatter_kernel() {
    int p = blockIdx.x * 256 + threadIdx.x;
    if (p >= PAIRS) return;
    int e = g_pair_e[p];
    int slot = g_off[e] + atomicAdd(&g_cursor[e], 1);
    g_pair_slot[p] = slot;
    g_rows_token[slot] = p >> 1;
}

// ---------------- kernel: weight split + transpose (tc path only) ----------------
__global__ __launch_bounds__(256) void wsplit_kernel(const float* __restrict__ W,
                                                     __nv_bfloat16* __restrict__ Wh,
                                                     __nv_bfloat16* __restrict__ Wl,
                                                     int K, int N) {
#if HAS_TC
    __shared__ float tile[64][65];
    const int e = blockIdx.z;
    const int K0 = blockIdx.y * 64, N0 = blockIdx.x * 64;
    const float* src = W + ((size_t)e * K + K0) * N + N0;
    const int t = threadIdx.x;
    const int r = t >> 4, c4 = (t & 15) * 4;
#pragma unroll
    for (int j = 0; j < 4; ++j) {
        int rr = r + j * 16;
        const float4 v = *reinterpret_cast<const float4*>(src + (size_t)rr * N + c4);
        tile[rr][c4 + 0] = v.x; tile[rr][c4 + 1] = v.y;
        tile[rr][c4 + 2] = v.z; tile[rr][c4 + 3] = v.w;
    }
    __syncthreads();
#pragma unroll
    for (int j = 0; j < 4; ++j) {
        int nn = r + j * 16;
        float v0 = tile[c4 + 0][nn], v1 = tile[c4 + 1][nn];
        float v2 = tile[c4 + 2][nn], v3 = tile[c4 + 3][nn];
        __nv_bfloat16 h0 = __float2bfloat16_rn(v0), h1 = __float2bfloat16_rn(v1);
        __nv_bfloat16 h2 = __float2bfloat16_rn(v2), h3 = __float2bfloat16_rn(v3);
        __nv_bfloat16 l0 = __float2bfloat16_rn(v0 - __bfloat162float(h0));
        __nv_bfloat16 l1 = __float2bfloat16_rn(v1 - __bfloat162float(h1));
        __nv_bfloat16 l2 = __float2bfloat16_rn(v2 - __bfloat162float(h2));
        __nv_bfloat16 l3 = __float2bfloat16_rn(v3 - __bfloat16_as_ushort(h3) * 0.f - __bfloat162float(h3));
        size_t out = ((size_t)e * N + N0 + nn) * K + K0 + c4;
        *reinterpret_cast<uint2*>(Wh + out) = make_uint2(pack_bf16(h0, h1), pack_bf16(h2, h3));
        *reinterpret_cast<uint2*>(Wl + out) = make_uint2(pack_bf16(l0, l1), pack_bf16(l2, l3));
    }
#endif
}

// ---------------- tcgen05 GEMM ----------------
#define BUF_STRIDE 98304
#define OFF_AL 16384
#define OFF_BH 32768
#define OFF_BL 65536
#define OFF_TOK 196608
#define OFF_TMEM 197120
#define OFF_MBAR 197136
#define SMEM_DYN 198656

#define GEMM_IDESC ((1u << 4) | (1u << 7) | (1u << 10) | ((256u / 8) << 17) | ((128u / 16) << 24))

template <bool FIRST>
__global__ __launch_bounds__(256) void moe_gemm_tc(const __nv_bfloat16* __restrict__ Wh,
                                                   const __nv_bfloat16* __restrict__ Wl,
                                                   const float* __restrict__ bias) {
#if HAS_TC
    constexpr int KTOT = FIRST ? DM : DF;
    constexpr int NTOT = FIRST ? DF : DM;
    constexpr int NCHUNK = KTOT / 64;

    const int tileIdx = blockIdx.y;
    if (tileIdx >= g_num_tiles) return;
    const int e = g_tile_e[tileIdx];
    const int row0 = g_tile_r0[tileIdx];
    const int vrows = g_tile_valid[tileIdx];
    const int n0 = blockIdx.x * 256;

    extern __shared__ char dyn[];
    const uint32_t raw = smaddr(dyn);
    const uint32_t sbase = (raw + 1023u) & ~1023u;
    char* base_g = dyn + (sbase - raw);
    int* sTok = reinterpret_cast<int*>(base_g + OFF_TOK);

    const int t = threadIdx.x;

    if (t < 128) {
        if (FIRST) {
            int r = row0 + t;
            sTok[t] = (t < vrows) ? g_rows_token[r < PAIRS ? r : PAIRS - 1] : 0;
        }
    }
    if (t == 0) {
        mbar_init(sbase + OFF_MBAR, 1);
        mbar_init(sbase + OFF_MBAR + 8, 1);
    }
    if (t < 32) {
        tc_alloc(sbase + OFF_TMEM, 256);
        tc_relinq();
    }
    __syncthreads();

    uint32_t tmem;
    asm volatile("ld.shared.b32 %0, [%1];" : "=r"(tmem) : "r"(sbase + OFF_TMEM));

    const int arow = t >> 1;
    const int ac0 = (t & 1) * 4;
    const __nv_bfloat16 *aSrcH, *aSrcL;
    if (FIRST) {
        int tok = sTok[arow];
        aSrcH = g_xh + (size_t)tok * DM;
        aSrcL = g_xl + (size_t)tok * DM;
    } else {
        int rg = row0 + arow; if (rg > PAIRS - 1) rg = PAIRS - 1;
        aSrcH = g_Hh + (size_t)rg * DF;
        aSrcL = g_Hl + (size_t)rg * DF;
    }
    const __nv_bfloat16* bSrcH = Wh + ((size_t)e * NTOT + n0 + t) * KTOT;
    const __nv_bfloat16* bSrcL = Wl + ((size_t)e * NTOT + n0 + t) * KTOT;

    const uint32_t aSw = arow * 128;
    const uint32_t bSw = t * 128;
    const int aX = arow & 7, bX = t & 7;

    uint64_t dAh[2], dAl[2], dBh[2], dBl[2];
#pragma unroll
    for (int s = 0; s < 2; ++s) {
        uint32_t b = sbase + s * BUF_STRIDE;
        dAh[s] = mk_desc(b);
        dAl[s] = mk_desc(b + OFF_AL);
        dBh[s] = mk_desc(b + OFF_BH);
        dBl[s] = mk_desc(b + OFF_BL);
    }

    auto load_chunk = [&](int s, int k0) {
        uint32_t bb = sbase + s * BUF_STRIDE;
#pragma unroll
        for (int c = 0; c < 4; ++c) {
            int cc = ac0 + c;
            uint32_t d = aSw + (uint32_t)((cc ^ aX) * 16);
            cpa16(bb + d, aSrcH + k0 + cc * 8);
            cpa16(bb + OFF_AL + d, aSrcL + k0 + cc * 8);
        }
#pragma unroll
        for (int c = 0; c < 8; ++c) {
            uint32_t d = bSw + (uint32_t)((c ^ bX) * 16);
            cpa16(bb + OFF_BH + d, bSrcH + k0 + c * 8);
            cpa16(bb + OFF_BL + d, bSrcL + k0 + c * 8);
        }
        cpa_commit();
    };

    load_chunk(0, 0);

    uint32_t ph[2] = {0, 0};
    const uint32_t mb0 = sbase + OFF_MBAR;

#pragma unroll 1
    for (int i = 0; i < NCHUNK; ++i) {
        const int b = i & 1;
        cpa_wait0();
        fence_async_smem();
        __syncthreads();
        if (t < 32) {
            if (elect_one()) {
#pragma unroll
                for (int ks = 0; ks < 4; ++ks) {
                    uint64_t oa = (uint64_t)(ks * 2);
                    uint32_t en0 = (i == 0 && ks == 0) ? 0u : 1u;
                    tc_mma_f16_ss(tmem, dAh[b] + oa, dBh[b] + oa, GEMM_IDESC, en0);
                    tc_mma_f16_ss(tmem, dAh[b] + oa, dBl[b] + oa, GEMM_IDESC, 1u);
                    tc_mma_f16_ss(tmem, dAl[b] + oa, dBh[b] + oa, GEMM_IDESC, 1u);
                }
                tc_commit(mb0 + b * 8);
            }
        }
        if (i + 1 < NCHUNK) {
            const int nb = b ^ 1;
            if (i >= 1) { mbar_wait(mb0 + nb * 8, ph[nb]); ph[nb] ^= 1; }
            load_chunk(nb, (i + 1) * 64);
        }
    }
    {
        const int b2 = (NCHUNK - 2) & 1;
        mbar_wait(mb0 + b2 * 8, ph[b2]); ph[b2] ^= 1;
        const int b1 = (NCHUNK - 1) & 1;
        mbar_wait(mb0 + b1 * 8, ph[b1]);
    }
    tc_fence_after();

    // epilogue
    const int w = t >> 5, lane = t & 31;
    const int rloc = (w & 3) * 32 + lane;
    const int cbase = (w >> 2) * 128;
    const bool valid = rloc < vrows;
    const int rowg = row0 + rloc;
    const float* bn = bias + (size_t)e * NTOT + n0 + cbase;

#pragma unroll
    for (int j = 0; j < 4; ++j) {
        uint32_t dr[32];
        tc_ld_x32(dr, tmem + cbase + j * 32);
        tc_wait_ld();
        if (valid) {
            int nb = cbase + j * 32;
            if (FIRST) {
                __nv_bfloat16* oH = g_Hh + (size_t)rowg * DF + n0 + nb;
                __nv_bfloat16* oL = g_Hl + (size_t)rowg * DF + n0 + nb;
#pragma unroll
                for (int c = 0; c < 32; c += 2) {
                    float v0 = gelu_exact(__uint_as_float(dr[c]) + bn[j * 32 + c]);
                    float v1 = gelu_exact(__uint_as_float(dr[c + 1]) + bn[j * 32 + c + 1]);
                    __nv_bfloat16 h0 = __float2bfloat16_rn(v0);
                    __nv_bfloat16 h1 = __float2bfloat16_rn(v1);
                    *reinterpret_cast<uint32_t*>(oH + c) = pack_bf16(h0, h1);
                    __nv_bfloat16 l0 = __float2bfloat16_rn(v0 - __bfloat162float(h0));
                    __nv_bfloat16 l1 = __float2bfloat16_rn(v1 - __bfloat162float(h1));
                    *reinterpret_cast<uint32_t*>(oL + c) = pack_bf16(l0, l1);
                }
            } else {
                float* oY = g_Y + (size_t)rowg * DM + n0 + nb;
#pragma unroll
                for (int c = 0; c < 32; c += 2) {
                    float v0 = __uint_as_float(dr[c]) + bn[j * 32 + c];
                    float v1 = __uint_as_float(dr[c + 1]) + bn[j * 32 + c + 1];
                    *reinterpret_cast<float2*>(oY + c) = make_float2(v0, v1);
                }
            }
        }
    }

    __syncthreads();
    if (t == 0) { mbar_inval(mb0); mbar_inval(mb0 + 8); }
    if (t < 32) tc_dealloc(tmem, 256);
#endif  // HAS_TC
}

// ---------------- fallback GEMM (round-1 mma.sync, only when tcgen05 absent) ----------------
template <bool FIRST>
__global__ __launch_bounds__(256) void moe_gemm_fb(const float* __restrict__ W,
                                                   const float* __restrict__ bias) {
#if !HAS_TC
    constexpr int KTOT = FIRST ? DM : DF;
    constexpr int LDW  = FIRST ? DF : DM;
    const int tileIdx = blockIdx.y;
    if (tileIdx >= g_num_tiles) return;
    const int e = g_tile_e[tileIdx];
    const int row0 = g_tile_r0[tileIdx];
    const int vrows = g_tile_valid[tileIdx];
    const int n0 = blockIdx.x * 128;
    const float* Wn = W + (size_t)e * KTOT * LDW + n0;
    const float* bn = bias + (size_t)e * LDW + n0;

    __shared__ __align__(16) __nv_bfloat16 sAh[128 * 40];
    __shared__ __align__(16) __nv_bfloat16 sAl[128 * 40];
    __shared__ __align__(16) __nv_bfloat16 sBh[32 * 136];
    __shared__ __align__(16) __nv_bfloat16 sBl[32 * 136];
    __shared__ int sTok[128];

    const int t = threadIdx.x;
    if (FIRST) {
        if (t < 128) {
            int r = row0 + t;
            sTok[t] = (t < vrows) ? g_rows_token[r < PAIRS ? r : PAIRS - 1] : 0;
        }
    }
    __syncthreads();

    float c[4][4][4];
#pragma unroll
    for (int a = 0; a < 4; ++a)
#pragma unroll
        for (int b = 0; b < 4; ++b)
#pragma unroll
            for (int q = 0; q < 4; ++q) c[a][b][q] = 0.f;

    const int lane = t & 31, warp = t >> 5;
    const int wm = warp >> 2, wn = warp & 3;
    const int m0 = wm * 64;
    const int sub = t & 15, rgrp = t >> 4;

    for (int k0 = 0; k0 < KTOT; k0 += 32) {
        __syncthreads();
#pragma unroll
        for (int rr = 0; rr < 8; ++rr) {
            int r = rr * 16 + rgrp;
            const uint32_t *ph, *pl;
            if (FIRST) {
                int tok = sTok[r];
                ph = reinterpret_cast<const uint32_t*>(g_xh + (size_t)tok * DM + k0);
                pl = reinterpret_cast<const uint32_t*>(g_xl + (size_t)tok * DM + k0);
            } else {
                int rg = row0 + r; if (rg > PAIRS - 1) rg = PAIRS - 1;
                ph = reinterpret_cast<const uint32_t*>(g_Hh + (size_t)rg * DF + k0);
                pl = reinterpret_cast<const uint32_t*>(g_Hl + (size_t)rg * DF + k0);
            }
            *reinterpret_cast<uint32_t*>(&sAh[r * 40 + sub * 2]) = ph[sub];
            *reinterpret_cast<uint32_t*>(&sAl[r * 40 + sub * 2]) = pl[sub];
        }
#pragma unroll
        for (int i = 0; i < 4; ++i) {
            int lin = (i * 256 + t) * 4;
            int kr = lin >> 7;
            int nc = lin & 127;
            const float4 v = *reinterpret_cast<const float4*>(Wn + (size_t)(k0 + kr) * LDW + nc);
            __nv_bfloat16 h0 = __float2bfloat16_rn(v.x);
            __nv_bfloat16 h1 = __float2bfloat16_rn(v.y);
            __nv_bfloat16 h2 = __float2bfloat16_rn(v.z);
            __nv_bfloat16 h3 = __float2bfloat16_rn(v.w);
            __nv_bfloat16 l0 = __float2bfloat16_rn(v.x - __bfloat162float(h0));
            __nv_bfloat16 l1 = __float2bfloat16_rn(v.y - __bfloat162float(h1));
            __nv_bfloat16 l2 = __float2bfloat16_rn(v.z - __bfloat162float(h2));
            __nv_bfloat16 l3 = __float2bfloat16_rn(v.w - __bfloat162float(h3));
            *reinterpret_cast<uint2*>(&sBh[kr * 136 + nc]) = make_uint2(pack_bf16(h0, h1), pack_bf16(h2, h3));
            *reinterpret_cast<uint2*>(&sBl[kr * 136 + nc]) = make_uint2(pack_bf16(l0, l1), pack_bf16(l2, l3));
        }
        __syncthreads();

#pragma unroll
        for (int ks = 0; ks < 2; ++ks) {
            uint32_t ah[4][4], al[4][4], bh[4][2], bl[4][2];
            {
                int arow = lane & 15;
                int acol = ks * 16 + (lane >> 4) * 8;
#pragma unroll
                for (int fm = 0; fm < 4; ++fm) {
                    ldsm4(ah[fm], smaddr(&sAh[(m0 + fm * 16 + arow) * 40 + acol]));
                    ldsm4(al[fm], smaddr(&sAl[(m0 + fm * 16 + arow) * 40 + acol]));
                }
                int brow = ks * 16 + (lane & 15);
                int bcol = wn * 32 + (lane >> 4) * 8;
#pragma unroll
                for (int hb = 0; hb < 2; ++hb) {
                    uint32_t r[4];
                    ldsm4t(r, smaddr(&sBh[brow * 136 + bcol + hb * 16]));
                    bh[2 * hb][0] = r[0]; bh[2 * hb][1] = r[1];
                    bh[2 * hb + 1][0] = r[2]; bh[2 * hb + 1][1] = r[3];
                    ldsm4t(r, smaddr(&sBl[brow * 136 + bcol + hb * 16]));
                    bl[2 * hb][0] = r[0]; bl[2 * hb][1] = r[1];
                    bl[2 * hb + 1][0] = r[2]; bl[2 * hb + 1][1] = r[3];
                }
            }
#pragma unroll
            for (int fm = 0; fm < 4; ++fm)
#pragma unroll
                for (int fn = 0; fn < 4; ++fn) {
                    mma16816(c[fm][fn], ah[fm], bh[fn]);
                    mma16816(c[fm][fn], ah[fm], bl[fn]);
                    mma16816(c[fm][fn], al[fm], bh[fn]);
                }
        }
    }

    const int lgrp = lane >> 2, lq = lane & 3;
#pragma unroll
    for (int fm = 0; fm < 4; ++fm) {
        int rl = m0 + fm * 16 + lgrp;
#pragma unroll
        for (int fn = 0; fn < 4; ++fn) {
            int nc = wn * 32 + fn * 8 + lq * 2;
            float bv0 = bn[nc], bv1 = bn[nc + 1];
            float* cc = c[fm][fn];
#pragma unroll
            for (int h = 0; h < 2; ++h) {
                int rloc = rl + h * 8;
                if (rloc < vrows) {
                    int row = row0 + rloc;
                    float v0 = cc[h * 2 + 0] + bv0;
                    float v1 = cc[h * 2 + 1] + bv1;
                    if (FIRST) {
                        v0 = gelu_exact(v0);
                        v1 = gelu_exact(v1);
                        __nv_bfloat16 h0 = __float2bfloat16_rn(v0);
                        __nv_bfloat16 h1 = __float2bfloat16_rn(v1);
                        *reinterpret_cast<uint32_t*>(&g_Hh[(size_t)row * DF + n0 + nc]) = pack_bf16(h0, h1);
                        __nv_bfloat16 l0 = __float2bfloat16_rn(v0 - __bfloat162float(h0));
                        __nv_bfloat16 l1 = __float2bfloat16_rn(v1 - __bfloat162float(h1));
                        *reinterpret_cast<uint32_t*>(&g_Hl[(size_t)row * DF + n0 + nc]) = pack_bf16(l0, l1);
                    } else {
                        *reinterpret_cast<float2*>(&g_Y[(size_t)row * DM + n0 + nc]) = make_float2(v0, v1);
                    }
                }
            }
        }
    }
#endif  // !HAS_TC
}

// ---------------- kernel: weighted combine ----------------
__global__ __launch_bounds__(256) void combine_kernel(float* __restrict__ out) {
    const int tk = blockIdx.x;
    const int d = threadIdx.x * 4;
    int s0 = g_pair_slot[2 * tk], s1 = g_pair_slot[2 * tk + 1];
    float w0 = g_pair_w[2 * tk], w1 = g_pair_w[2 * tk + 1];
    const float4 a = *reinterpret_cast<const float4*>(&g_Y[(size_t)s0 * DM + d]);
    const float4 b = *reinterpret_cast<const float4*>(&g_Y[(size_t)s1 * DM + d]);
    float4 o;
    o.x = w0 * a.x + w1 * b.x;
    o.y = w0 * a.y + w1 * b.y;
    o.z = w0 * a.z + w1 * b.z;
    o.w = w0 * a.w + w1 * b.w;
    *reinterpret_cast<float4*>(&out[(size_t)tk * DM + d]) = o;
}

// ---------------- launch ----------------
extern "C" void kernel_launch(void* const* d_in, const int* in_sizes, int n_in,
                              void* d_out, int out_size) {
    const float* x  = (const float*)d_in[0];
    const float* gw = (const float*)d_in[1];
    const float* w1 = (const float*)d_in[2];
    const float* b1 = (const float*)d_in[3];
    const float* w2 = (const float*)d_in[4];
    const float* b2 = (const float*)d_in[5];
    float* out = (float*)d_out;

    cudaFuncSetAttribute(moe_gemm_tc<true>,  cudaFuncAttributeMaxDynamicSharedMemorySize, SMEM_DYN);
    cudaFuncSetAttribute(moe_gemm_tc<false>, cudaFuncAttributeMaxDynamicSharedMemorySize, SMEM_DYN);

    __nv_bfloat16 *w1h, *w1l, *w2h, *w2l;
    cudaGetSymbolAddress((void**)&w1h, g_w1h);
    cudaGetSymbolAddress((void**)&w1l, g_w1l);
    cudaGetSymbolAddress((void**)&w2h, g_w2h);
    cudaGetSymbolAddress((void**)&w2l, g_w2l);

    zero_kernel<<<1, 32>>>();
    gate_kernel<<<T_TOKENS, 256>>>(x, gw);
    scan_kernel<<<1, 32>>>();
    scatter_kernel<<<PAIRS / 256, 256>>>();
    // tc-path weight preprocessing (no-op bodies when tcgen05 unavailable)
    wsplit_kernel<<<dim3(DF / 64, DM / 64, NE), 256>>>(w1, w1h, w1l, DM, DF);
    wsplit_kernel<<<dim3(DM / 64, DF / 64, NE), 256>>>(w2, w2h, w2l, DF, DM);
    // layer 1: exactly one of these two has a body in the selected binary
    moe_gemm_tc<true><<<dim3(DF / 256, 136), 256, SMEM_DYN>>>(w1h, w1l, b1);
    moe_gemm_fb<true><<<dim3(DF / 128, 136), 256>>>(w1, b1);
    // layer 2
    moe_gemm_tc<false><<<dim3(DM / 256, 136), 256, SMEM_DYN>>>(w2h, w2l, b2);
    moe_gemm_fb<false><<<dim3(DM / 128, 136), 256>>>(w2, b2);
    combine_kernel<<<T_TOKENS, 256>>>(out);
}

// round 5
// speedup vs baseline: 3.4667x; 1.0105x over previous
#include <cuda_runtime.h>
#include <cuda_bf16.h>
#include <stdint.h>

#define T_TOKENS 8192
#define DM 1024
#define DF 4096
#define NE 8
#define PAIRS 16384
#define MAXTILES 144

// tcgen05 availability: only in the arch-SPECIFIC device pass (sm_103a / sm_100a).
#if defined(__CUDA_ARCH__) && (defined(__CUDA_ARCH_FEAT_SM103_ALL) || defined(__CUDA_ARCH_FEAT_SM100_ALL) || defined(__CUDA_ARCH_SPECIFIC__))
#define HAS_TC 1
#else
#define HAS_TC 0
#endif

// ---------------- scratch (device globals; no allocations) ----------------
__device__ __align__(128) __nv_bfloat16 g_xh[(size_t)T_TOKENS * DM];
__device__ __align__(128) __nv_bfloat16 g_xl[(size_t)T_TOKENS * DM];
__device__ __align__(128) __nv_bfloat16 g_Hh[(size_t)PAIRS * DF];
__device__ __align__(128) __nv_bfloat16 g_Hl[(size_t)PAIRS * DF];
__device__ __align__(128) float         g_Y[(size_t)PAIRS * DM];

// pre-split, pre-transposed weights: [E][N][K] bf16 hi/lo (tc path only)
__device__ __align__(128) __nv_bfloat16 g_w1h[(size_t)NE * DM * DF];
__device__ __align__(128) __nv_bfloat16 g_w1l[(size_t)NE * DM * DF];
__device__ __align__(128) __nv_bfloat16 g_w2h[(size_t)NE * DF * DM];
__device__ __align__(128) __nv_bfloat16 g_w2l[(size_t)NE * DF * DM];

__device__ int   g_pair_e[PAIRS];
__device__ float g_pair_w[PAIRS];
__device__ int   g_pair_slot[PAIRS];
__device__ int   g_rows_token[PAIRS];

__device__ int g_counts[NE];
__device__ int g_off[NE + 1];
__device__ int g_tile_e[MAXTILES];
__device__ int g_tile_r0[MAXTILES];
__device__ int g_tile_valid[MAXTILES];
__device__ int g_num_tiles;

// ---------------- shared helpers ----------------
__device__ __forceinline__ uint32_t smaddr(const void* p) {
    return (uint32_t)__cvta_generic_to_shared(p);
}
__device__ __forceinline__ uint32_t pack_bf16(__nv_bfloat16 a, __nv_bfloat16 b) {
    return (uint32_t)__bfloat16_as_ushort(a) | ((uint32_t)__bfloat16_as_ushort(b) << 16);
}
__device__ __forceinline__ float gelu_exact(float v) {
    return 0.5f * v * (1.0f + erff(v * 0.70710678118654752f));
}

#if HAS_TC
// ---------------- tcgen05-path helpers ----------------
__device__ __forceinline__ uint32_t elect_one() {
    uint32_t pred;
    asm volatile("{\n\t.reg .pred p;\n\telect.sync _|p, 0xFFFFFFFF;\n\tselp.b32 %0, 1, 0, p;\n\t}"
                 : "=r"(pred));
    return pred;
}
__device__ __forceinline__ void cpa16(uint32_t dst, const void* src) {
    asm volatile("cp.async.cg.shared.global [%0], [%1], 16;\n" :: "r"(dst), "l"(src));
}
__device__ __forceinline__ void cpa_commit() {
    asm volatile("cp.async.commit_group;\n" ::: "memory");
}
template <int N>
__device__ __forceinline__ void cpa_waitn() {
    asm volatile("cp.async.wait_group %0;\n" :: "n"(N) : "memory");
}
__device__ __forceinline__ void fence_async_smem() {
    asm volatile("fence.proxy.async.shared::cta;" ::: "memory");
}
__device__ __forceinline__ void mbar_init(uint32_t addr, uint32_t cnt) {
    asm volatile("mbarrier.init.shared.b64 [%0], %1;" :: "r"(addr), "r"(cnt) : "memory");
}
__device__ __forceinline__ void mbar_inval(uint32_t addr) {
    asm volatile("mbarrier.inval.shared.b64 [%0];" :: "r"(addr) : "memory");
}
__device__ __forceinline__ void mbar_wait(uint32_t addr, uint32_t parity) {
    asm volatile(
        "{\n\t.reg .pred P1;\n"
        "WAIT_%=:\n\t"
        "mbarrier.try_wait.parity.acquire.cta.shared::cta.b64 P1, [%0], %1, 0x989680;\n\t"
        "@P1 bra.uni DONE_%=;\n\t"
        "bra.uni WAIT_%=;\n"
        "DONE_%=:\n\t}"
        :: "r"(addr), "r"(parity) : "memory");
}
__device__ __forceinline__ void tc_mma_f16_ss(uint32_t d, uint64_t a, uint64_t b,
                                              uint32_t idesc, uint32_t en) {
    asm volatile(
        "{\n\t.reg .pred p;\n\tsetp.ne.u32 p, %5, 0;\n\t"
        "tcgen05.mma.cta_group::1.kind::f16 [%0], %1, %2, %3, {%4, %4, %4, %4}, p;\n\t}"
        :: "r"(d), "l"(a), "l"(b), "r"(idesc), "r"(0u), "r"(en) : "memory");
}
__device__ __forceinline__ void tc_commit(uint32_t mbar) {
    asm volatile("tcgen05.commit.cta_group::1.mbarrier::arrive::one.shared::cluster.b64 [%0];"
                 :: "r"(mbar) : "memory");
}
__device__ __forceinline__ void tc_alloc(uint32_t smem_slot, uint32_t ncols) {
    asm volatile("tcgen05.alloc.cta_group::1.sync.aligned.shared::cta.b32 [%0], %1;"
                 :: "r"(smem_slot), "r"(ncols) : "memory");
}
__device__ __forceinline__ void tc_dealloc(uint32_t tmem, uint32_t ncols) {
    asm volatile("tcgen05.dealloc.cta_group::1.sync.aligned.b32 %0, %1;" :: "r"(tmem), "r"(ncols));
}
__device__ __forceinline__ void tc_relinq() {
    asm volatile("tcgen05.relinquish_alloc_permit.cta_group::1.sync.aligned;");
}
__device__ __forceinline__ void tc_fence_after() {
    asm volatile("tcgen05.fence::after_thread_sync;" ::: "memory");
}
__device__ __forceinline__ void tc_wait_ld() {
    asm volatile("tcgen05.wait::ld.sync.aligned;" ::: "memory");
}
__device__ __forceinline__ void tc_ld_x32(uint32_t* r, uint32_t addr) {
    asm volatile(
        "tcgen05.ld.sync.aligned.32x32b.x32.b32 "
        "{%0, %1, %2, %3, %4, %5, %6, %7, %8, %9, %10, %11, %12, %13, %14, %15, "
        " %16, %17, %18, %19, %20, %21, %22, %23, %24, %25, %26, %27, %28, %29, %30, %31}, [%32];"
        : "=r"(r[0]), "=r"(r[1]), "=r"(r[2]), "=r"(r[3]), "=r"(r[4]), "=r"(r[5]), "=r"(r[6]), "=r"(r[7]),
          "=r"(r[8]), "=r"(r[9]), "=r"(r[10]), "=r"(r[11]), "=r"(r[12]), "=r"(r[13]), "=r"(r[14]), "=r"(r[15]),
          "=r"(r[16]), "=r"(r[17]), "=r"(r[18]), "=r"(r[19]), "=r"(r[20]), "=r"(r[21]), "=r"(r[22]), "=r"(r[23]),
          "=r"(r[24]), "=r"(r[25]), "=r"(r[26]), "=r"(r[27]), "=r"(r[28]), "=r"(r[29]), "=r"(r[30]), "=r"(r[31])
        : "r"(addr));
}
// SW128 K-major descriptor base (LBO=1, SBO=64, version=1, layout SW128)
__device__ __forceinline__ uint64_t mk_desc(uint32_t addr) {
    const uint64_t DBASE = (2ULL << 61) | (1ULL << 46) | (64ULL << 32) | (1ULL << 16);
    return DBASE | (uint64_t)((addr >> 4) & 0x3FFF);
}
#endif  // HAS_TC

#if !HAS_TC
// ---------------- fallback-path helpers (mma.sync) ----------------
__device__ __forceinline__ void ldsm4(uint32_t* r, uint32_t addr) {
    asm volatile("ldmatrix.sync.aligned.m8n8.x4.shared.b16 {%0,%1,%2,%3}, [%4];\n"
                 : "=r"(r[0]), "=r"(r[1]), "=r"(r[2]), "=r"(r[3]) : "r"(addr));
}
__device__ __forceinline__ void ldsm4t(uint32_t* r, uint32_t addr) {
    asm volatile("ldmatrix.sync.aligned.m8n8.x4.trans.shared.b16 {%0,%1,%2,%3}, [%4];\n"
                 : "=r"(r[0]), "=r"(r[1]), "=r"(r[2]), "=r"(r[3]) : "r"(addr));
}
__device__ __forceinline__ void mma16816(float* c, const uint32_t* a, const uint32_t* b) {
    asm volatile(
        "mma.sync.aligned.m16n8k16.row.col.f32.bf16.bf16.f32 "
        "{%0,%1,%2,%3}, {%4,%5,%6,%7}, {%8,%9}, {%0,%1,%2,%3};\n"
        : "+f"(c[0]), "+f"(c[1]), "+f"(c[2]), "+f"(c[3])
        : "r"(a[0]), "r"(a[1]), "r"(a[2]), "r"(a[3]), "r"(b[0]), "r"(b[1]));
}
#endif  // !HAS_TC

// ---------------- kernel: gating + x -> bf16 hi/lo (no atomics) ----------------
__global__ __launch_bounds__(256) void gate_kernel(const float* __restrict__ x,
                                                   const float* __restrict__ gw) {
    const int tk = blockIdx.x;
    const int tid = threadIdx.x;
    const float* xr = x + (size_t)tk * DM;

    float p[NE];
#pragma unroll
    for (int e = 0; e < NE; ++e) p[e] = 0.f;
    float xv[4];
#pragma unroll
    for (int j = 0; j < 4; ++j) {
        int i = j * 256 + tid;
        float v = xr[i];
        xv[j] = v;
#pragma unroll
        for (int e = 0; e < NE; ++e) p[e] += v * gw[e * DM + i];
    }
#pragma unroll
    for (int j = 0; j < 4; ++j) {
        int i = j * 256 + tid;
        __nv_bfloat16 h = __float2bfloat16_rn(xv[j]);
        g_xh[(size_t)tk * DM + i] = h;
        g_xl[(size_t)tk * DM + i] = __float2bfloat16_rn(xv[j] - __bfloat162float(h));
    }
#pragma unroll
    for (int e = 0; e < NE; ++e)
#pragma unroll
        for (int o = 16; o > 0; o >>= 1) p[e] += __shfl_xor_sync(0xffffffffu, p[e], o);

    __shared__ float sRed[8][NE];
    int lane = tid & 31, w = tid >> 5;
    if (lane == 0) {
#pragma unroll
        for (int e = 0; e < NE; ++e) sRed[w][e] = p[e];
    }
    __syncthreads();
    if (tid == 0) {
        float lg[NE];
#pragma unroll
        for (int e = 0; e < NE; ++e) {
            float s = 0.f;
#pragma unroll
            for (int ww = 0; ww < 8; ++ww) s += sRed[ww][e];
            lg[e] = s;
        }
        float m = lg[0];
#pragma unroll
        for (int e = 1; e < NE; ++e) m = fmaxf(m, lg[e]);
        float ex[NE], S = 0.f;
#pragma unroll
        for (int e = 0; e < NE; ++e) { ex[e] = expf(lg[e] - m); S += ex[e]; }
        int i0 = 0;
#pragma unroll
        for (int e = 1; e < NE; ++e) if (ex[e] > ex[i0]) i0 = e;
        int i1 = (i0 == 0) ? 1 : 0;
#pragma unroll
        for (int e = 0; e < NE; ++e) if (e != i0 && ex[e] > ex[i1]) i1 = e;
        float p0 = ex[i0] / S, p1 = ex[i1] / S;
        float den = p0 + p1 + 1e-9f;
        g_pair_e[2 * tk] = i0;     g_pair_w[2 * tk] = p0 / den;
        g_pair_e[2 * tk + 1] = i1; g_pair_w[2 * tk + 1] = p1 / den;
    }
}

// ---------------- kernel: counting sort (counts + scan + tiles + scatter) ----------------
__global__ __launch_bounds__(256) void sortscan_kernel() {
    __shared__ uint16_t loc[256][NE];
    __shared__ int s_cnt[NE];
    __shared__ int s_off[NE];
    const int t = threadIdx.x;
    const int p0 = t * 64;

    int lc[NE];
#pragma unroll
    for (int e = 0; e < NE; ++e) lc[e] = 0;
    for (int i = 0; i < 64; ++i) lc[g_pair_e[p0 + i]]++;
#pragma unroll
    for (int e = 0; e < NE; ++e) loc[t][e] = (uint16_t)lc[e];
    __syncthreads();

    if (t < NE) {
        int run = 0;
        for (int i = 0; i < 256; ++i) {
            int c = loc[i][t];
            loc[i][t] = (uint16_t)run;
            run += c;
        }
        s_cnt[t] = run;
        g_counts[t] = run;
    }
    __syncthreads();

    if (t == 0) {
        int off = 0, nt = 0;
        for (int e = 0; e < NE; ++e) {
            g_off[e] = off;
            s_off[e] = off;
            int c = s_cnt[e];
            int tiles = (c + 127) >> 7;
            for (int i = 0; i < tiles; ++i) {
                g_tile_e[nt] = e;
                g_tile_r0[nt] = off + i * 128;
                int v = c - i * 128;
                g_tile_valid[nt] = v > 128 ? 128 : v;
                ++nt;
            }
            off += c;
        }
        g_off[NE] = off;
        g_num_tiles = nt;
    }
    __syncthreads();

    int run[NE];
#pragma unroll
    for (int e = 0; e < NE; ++e) run[e] = s_off[e] + (int)loc[t][e];
    for (int i = 0; i < 64; ++i) {
        int p = p0 + i;
        int e = g_pair_e[p];
        int slot = run[e]++;
        g_pair_slot[p] = slot;
        g_rows_token[slot] = p >> 1;
    }
}

// ---------------- kernel: weight split + transpose (tc path only) ----------------
__global__ __launch_bounds__(256) void wsplit_kernel(const float* __restrict__ W,
                                                     __nv_bfloat16* __restrict__ Wh,
                                                     __nv_bfloat16* __restrict__ Wl,
                                                     int K, int N) {
#if HAS_TC
    __shared__ float tile[64][65];
    const int e = blockIdx.z;
    const int K0 = blockIdx.y * 64, N0 = blockIdx.x * 64;
    const float* src = W + ((size_t)e * K + K0) * N + N0;
    const int t = threadIdx.x;
    const int r = t >> 4, c4 = (t & 15) * 4;
#pragma unroll
    for (int j = 0; j < 4; ++j) {
        int rr = r + j * 16;
        const float4 v = *reinterpret_cast<const float4*>(src + (size_t)rr * N + c4);
        tile[rr][c4 + 0] = v.x; tile[rr][c4 + 1] = v.y;
        tile[rr][c4 + 2] = v.z; tile[rr][c4 + 3] = v.w;
    }
    __syncthreads();
#pragma unroll
    for (int j = 0; j < 4; ++j) {
        int nn = r + j * 16;
        float v0 = tile[c4 + 0][nn], v1 = tile[c4 + 1][nn];
        float v2 = tile[c4 + 2][nn], v3 = tile[c4 + 3][nn];
        __nv_bfloat16 h0 = __float2bfloat16_rn(v0), h1 = __float2bfloat16_rn(v1);
        __nv_bfloat16 h2 = __float2bfloat16_rn(v2), h3 = __float2bfloat16_rn(v3);
        __nv_bfloat16 l0 = __float2bfloat16_rn(v0 - __bfloat162float(h0));
        __nv_bfloat16 l1 = __float2bfloat16_rn(v1 - __bfloat162float(h1));
        __nv_bfloat16 l2 = __float2bfloat16_rn(v2 - __bfloat162float(h2));
        __nv_bfloat16 l3 = __float2bfloat16_rn(v3 - __bfloat162float(h3));
        size_t out = ((size_t)e * N + N0 + nn) * K + K0 + c4;
        *reinterpret_cast<uint2*>(Wh + out) = make_uint2(pack_bf16(h0, h1), pack_bf16(h2, h3));
        *reinterpret_cast<uint2*>(Wl + out) = make_uint2(pack_bf16(l0, l1), pack_bf16(l2, l3));
    }
#endif
}

// ---------------- tcgen05 GEMM ----------------
// BM=128, BN=256. 2 physical K=64 SW128 stages, pipelined at K=32 half granularity
// (4 logical slots, 4 mbarriers, prefetch distance 3 halves, cp.async wait_group 2).
#define BUF_STRIDE 98304
#define OFF_AL 16384
#define OFF_BH 32768
#define OFF_BL 65536
#define OFF_TOK 196608
#define OFF_TMEM 197120
#define OFF_MBAR 197152
#define SMEM_DYN 198656

#define GEMM_IDESC ((1u << 4) | (1u << 7) | (1u << 10) | ((256u / 8) << 17) | ((128u / 16) << 24))

template <bool FIRST>
__global__ __launch_bounds__(256) void moe_gemm_tc(const __nv_bfloat16* __restrict__ Wh,
                                                   const __nv_bfloat16* __restrict__ Wl,
                                                   const float* __restrict__ bias) {
#if HAS_TC
    constexpr int KTOT = FIRST ? DM : DF;
    constexpr int NTOT = FIRST ? DF : DM;
    constexpr int H = KTOT / 32;  // number of K=32 halves (32 or 128)

    const int tileIdx = blockIdx.y;
    if (tileIdx >= g_num_tiles) return;
    const int e = g_tile_e[tileIdx];
    const int row0 = g_tile_r0[tileIdx];
    const int vrows = g_tile_valid[tileIdx];
    const int n0 = blockIdx.x * 256;

    extern __shared__ char dyn[];
    const uint32_t raw = smaddr(dyn);
    const uint32_t sbase = (raw + 1023u) & ~1023u;
    char* base_g = dyn + (sbase - raw);
    int* sTok = reinterpret_cast<int*>(base_g + OFF_TOK);

    const int t = threadIdx.x;

    if (t < 128) {
        if (FIRST) {
            int r = row0 + t;
            sTok[t] = (t < vrows) ? g_rows_token[r < PAIRS ? r : PAIRS - 1] : 0;
        }
    }
    if (t == 0) {
#pragma unroll
        for (int s = 0; s < 4; ++s) mbar_init(sbase + OFF_MBAR + s * 8, 1);
    }
    if (t < 32) {
        tc_alloc(sbase + OFF_TMEM, 256);
        tc_relinq();
    }
    __syncthreads();

    uint32_t tmem;
    asm volatile("ld.shared.b32 %0, [%1];" : "=r"(tmem) : "r"(sbase + OFF_TMEM));

    // per-thread load coordinates
    const int arow = t >> 1;          // A row (0..127)
    const int av0 = (t & 1) * 2;      // A vec offset within half (0 or 2)
    const __nv_bfloat16 *aSrcH, *aSrcL;
    if (FIRST) {
        int tok = sTok[arow];
        aSrcH = g_xh + (size_t)tok * DM;
        aSrcL = g_xl + (size_t)tok * DM;
    } else {
        int rg = row0 + arow; if (rg > PAIRS - 1) rg = PAIRS - 1;
        aSrcH = g_Hh + (size_t)rg * DF;
        aSrcL = g_Hl + (size_t)rg * DF;
    }
    const __nv_bfloat16* bSrcH = Wh + ((size_t)e * NTOT + n0 + t) * KTOT;
    const __nv_bfloat16* bSrcL = Wl + ((size_t)e * NTOT + n0 + t) * KTOT;

    const uint32_t aSw = arow * 128;
    const uint32_t bSw = t * 128;
    const int aX = arow & 7, bX = t & 7;

    uint64_t dAh[2], dAl[2], dBh[2], dBl[2];
#pragma unroll
    for (int s = 0; s < 2; ++s) {
        uint32_t b = sbase + s * BUF_STRIDE;
        dAh[s] = mk_desc(b);
        dAl[s] = mk_desc(b + OFF_AL);
        dBh[s] = mk_desc(b + OFF_BH);
        dBl[s] = mk_desc(b + OFF_BL);
    }

    // load one K=32 half (48 KB) + commit group
    auto load_half = [&](int hh) {
        const int stage = (hh >> 1) & 1;
        const int half = hh & 1;
        const int k0 = (hh >> 1) * 64;
        const uint32_t bb = sbase + stage * BUF_STRIDE;
#pragma unroll
        for (int c = 0; c < 2; ++c) {
            int v = half * 4 + av0 + c;
            uint32_t d = aSw + (uint32_t)((v ^ aX) * 16);
            cpa16(bb + d, aSrcH + k0 + v * 8);
            cpa16(bb + OFF_AL + d, aSrcL + k0 + v * 8);
        }
#pragma unroll
        for (int c = 0; c < 4; ++c) {
            int v = half * 4 + c;
            uint32_t d = bSw + (uint32_t)((v ^ bX) * 16);
            cpa16(bb + OFF_BH + d, bSrcH + k0 + v * 8);
            cpa16(bb + OFF_BL + d, bSrcL + k0 + v * 8);
        }
        cpa_commit();
    };

    load_half(0);
    load_half(1);
    load_half(2);

    uint32_t ph[4] = {0, 0, 0, 0};
    const uint32_t mb0 = sbase + OFF_MBAR;

#pragma unroll 1
    for (int hh = 0; hh < H; ++hh) {
        const int rem = H - 1 - hh;
        if (rem >= 2) cpa_waitn<2>();
        else if (rem == 1) cpa_waitn<1>();
        else cpa_waitn<0>();
        fence_async_smem();
        __syncthreads();

        const int stage = (hh >> 1) & 1;
        const int half = hh & 1;
        if (t < 32) {
            if (elect_one()) {
#pragma unroll
                for (int ks2 = 0; ks2 < 2; ++ks2) {
                    const int ks = half * 2 + ks2;
                    const uint64_t oa = (uint64_t)(ks * 2);
                    const uint32_t en0 = (hh == 0 && ks2 == 0) ? 0u : 1u;
                    tc_mma_f16_ss(tmem, dAh[stage] + oa, dBh[stage] + oa, GEMM_IDESC, en0);
                    tc_mma_f16_ss(tmem, dAh[stage] + oa, dBl[stage] + oa, GEMM_IDESC, 1u);
                    tc_mma_f16_ss(tmem, dAl[stage] + oa, dBh[stage] + oa, GEMM_IDESC, 1u);
                }
                tc_commit(mb0 + (hh & 3) * 8);
            }
        }
        if (hh + 3 < H) {
            const int s = (hh + 3) & 3;
            if (hh >= 1) { mbar_wait(mb0 + s * 8, ph[s]); ph[s] ^= 1; }
            load_half(hh + 3);
        }
    }
    // drain outstanding MMA commits (halves H-4..H-1)
#pragma unroll
    for (int q = 4; q >= 1; --q) {
        const int s = (H - q) & 3;
        mbar_wait(mb0 + s * 8, ph[s]);
        ph[s] ^= 1;
    }
    tc_fence_after();
    __syncthreads();

    // ---------------- epilogue ----------------
    const int w = t >> 5, lane = t & 31;
    const int rloc = (w & 3) * 32 + lane;
    const int cbase = (w >> 2) * 128;
    const bool valid = rloc < vrows;
    const int rowg = row0 + rloc;
    const float* bn = bias + (size_t)e * NTOT + n0 + cbase;

#pragma unroll
    for (int j = 0; j < 4; ++j) {
        uint32_t dr[32];
        tc_ld_x32(dr, tmem + cbase + j * 32);
        tc_wait_ld();
        if (valid) {
            int nb = cbase + j * 32;
            if (FIRST) {
                __nv_bfloat16* oH = g_Hh + (size_t)rowg * DF + n0 + nb;
                __nv_bfloat16* oL = g_Hl + (size_t)rowg * DF + n0 + nb;
#pragma unroll
                for (int c = 0; c < 32; c += 2) {
                    float v0 = gelu_exact(__uint_as_float(dr[c]) + bn[j * 32 + c]);
                    float v1 = gelu_exact(__uint_as_float(dr[c + 1]) + bn[j * 32 + c + 1]);
                    __nv_bfloat16 h0 = __float2bfloat16_rn(v0);
                    __nv_bfloat16 h1 = __float2bfloat16_rn(v1);
                    *reinterpret_cast<uint32_t*>(oH + c) = pack_bf16(h0, h1);
                    __nv_bfloat16 l0 = __float2bfloat16_rn(v0 - __bfloat162float(h0));
                    __nv_bfloat16 l1 = __float2bfloat16_rn(v1 - __bfloat162float(h1));
                    *reinterpret_cast<uint32_t*>(oL + c) = pack_bf16(l0, l1);
                }
            } else {
                float* oY = g_Y + (size_t)rowg * DM + n0 + nb;
#pragma unroll
                for (int c = 0; c < 32; c += 2) {
                    float v0 = __uint_as_float(dr[c]) + bn[j * 32 + c];
                    float v1 = __uint_as_float(dr[c + 1]) + bn[j * 32 + c + 1];
                    *reinterpret_cast<float2*>(oY + c) = make_float2(v0, v1);
                }
            }
        }
    }

    __syncthreads();
    if (t == 0) {
#pragma unroll
        for (int s = 0; s < 4; ++s) mbar_inval(mb0 + s * 8);
    }
    if (t < 32) tc_dealloc(tmem, 256);
#endif  // HAS_TC
}

// ---------------- fallback GEMM (mma.sync, only when tcgen05 absent) ----------------
template <bool FIRST>
__global__ __launch_bounds__(256) void moe_gemm_fb(const float* __restrict__ W,
                                                   const float* __restrict__ bias) {
#if !HAS_TC
    constexpr int KTOT = FIRST ? DM : DF;
    constexpr int LDW  = FIRST ? DF : DM;
    const int tileIdx = blockIdx.y;
    if (tileIdx >= g_num_tiles) return;
    const int e = g_tile_e[tileIdx];
    const int row0 = g_tile_r0[tileIdx];
    const int vrows = g_tile_valid[tileIdx];
    const int n0 = blockIdx.x * 128;
    const float* Wn = W + (size_t)e * KTOT * LDW + n0;
    const float* bn = bias + (size_t)e * LDW + n0;

    __shared__ __align__(16) __nv_bfloat16 sAh[128 * 40];
    __shared__ __align__(16) __nv_bfloat16 sAl[128 * 40];
    __shared__ __align__(16) __nv_bfloat16 sBh[32 * 136];
    __shared__ __align__(16) __nv_bfloat16 sBl[32 * 136];
    __shared__ int sTok[128];

    const int t = threadIdx.x;
    if (FIRST) {
        if (t < 128) {
            int r = row0 + t;
            sTok[t] = (t < vrows) ? g_rows_token[r < PAIRS ? r : PAIRS - 1] : 0;
        }
    }
    __syncthreads();

    float c[4][4][4];
#pragma unroll
    for (int a = 0; a < 4; ++a)
#pragma unroll
        for (int b = 0; b < 4; ++b)
#pragma unroll
            for (int q = 0; q < 4; ++q) c[a][b][q] = 0.f;

    const int lane = t & 31, warp = t >> 5;
    const int wm = warp >> 2, wn = warp & 3;
    const int m0 = wm * 64;
    const int sub = t & 15, rgrp = t >> 4;

    for (int k0 = 0; k0 < KTOT; k0 += 32) {
        __syncthreads();
#pragma unroll
        for (int rr = 0; rr < 8; ++rr) {
            int r = rr * 16 + rgrp;
            const uint32_t *ph, *pl;
            if (FIRST) {
                int tok = sTok[r];
                ph = reinterpret_cast<const uint32_t*>(g_xh + (size_t)tok * DM + k0);
                pl = reinterpret_cast<const uint32_t*>(g_xl + (size_t)tok * DM + k0);
            } else {
                int rg = row0 + r; if (rg > PAIRS - 1) rg = PAIRS - 1;
                ph = reinterpret_cast<const uint32_t*>(g_Hh + (size_t)rg * DF + k0);
                pl = reinterpret_cast<const uint32_t*>(g_Hl + (size_t)rg * DF + k0);
            }
            *reinterpret_cast<uint32_t*>(&sAh[r * 40 + sub * 2]) = ph[sub];
            *reinterpret_cast<uint32_t*>(&sAl[r * 40 + sub * 2]) = pl[sub];
        }
#pragma unroll
        for (int i = 0; i < 4; ++i) {
            int lin = (i * 256 + t) * 4;
            int kr = lin >> 7;
            int nc = lin & 127;
            const float4 v = *reinterpret_cast<const float4*>(Wn + (size_t)(k0 + kr) * LDW + nc);
            __nv_bfloat16 h0 = __float2bfloat16_rn(v.x);
            __nv_bfloat16 h1 = __float2bfloat16_rn(v.y);
            __nv_bfloat16 h2 = __float2bfloat16_rn(v.z);
            __nv_bfloat16 h3 = __float2bfloat16_rn(v.w);
            __nv_bfloat16 l0 = __float2bfloat16_rn(v.x - __bfloat162float(h0));
            __nv_bfloat16 l1 = __float2bfloat16_rn(v.y - __bfloat162float(h1));
            __nv_bfloat16 l2 = __float2bfloat16_rn(v.z - __bfloat162float(h2));
            __nv_bfloat16 l3 = __float2bfloat16_rn(v.w - __bfloat162float(h3));
            *reinterpret_cast<uint2*>(&sBh[kr * 136 + nc]) = make_uint2(pack_bf16(h0, h1), pack_bf16(h2, h3));
            *reinterpret_cast<uint2*>(&sBl[kr * 136 + nc]) = make_uint2(pack_bf16(l0, l1), pack_bf16(l2, l3));
        }
        __syncthreads();

#pragma unroll
        for (int ks = 0; ks < 2; ++ks) {
            uint32_t ah[4][4], al[4][4], bh[4][2], bl[4][2];
            {
                int ar = lane & 15;
                int acol = ks * 16 + (lane >> 4) * 8;
#pragma unroll
                for (int fm = 0; fm < 4; ++fm) {
                    ldsm4(ah[fm], smaddr(&sAh[(m0 + fm * 16 + ar) * 40 + acol]));
                    ldsm4(al[fm], smaddr(&sAl[(m0 + fm * 16 + ar) * 40 + acol]));
                }
                int brow = ks * 16 + (lane & 15);
                int bcol = wn * 32 + (lane >> 4) * 8;
#pragma unroll
                for (int hb = 0; hb < 2; ++hb) {
                    uint32_t r[4];
                    ldsm4t(r, smaddr(&sBh[brow * 136 + bcol + hb * 16]));
                    bh[2 * hb][0] = r[0]; bh[2 * hb][1] = r[1];
                    bh[2 * hb + 1][0] = r[2]; bh[2 * hb + 1][1] = r[3];
                    ldsm4t(r, smaddr(&sBl[brow * 136 + bcol + hb * 16]));
                    bl[2 * hb][0] = r[0]; bl[2 * hb][1] = r[1];
                    bl[2 * hb + 1][0] = r[2]; bl[2 * hb + 1][1] = r[3];
                }
            }
#pragma unroll
            for (int fm = 0; fm < 4; ++fm)
#pragma unroll
                for (int fn = 0; fn < 4; ++fn) {
                    mma16816(c[fm][fn], ah[fm], bh[fn]);
                    mma16816(c[fm][fn], ah[fm], bl[fn]);
                    mma16816(c[fm][fn], al[fm], bh[fn]);
                }
        }
    }

    const int lgrp = lane >> 2, lq = lane & 3;
#pragma unroll
    for (int fm = 0; fm < 4; ++fm) {
        int rl = m0 + fm * 16 + lgrp;
#pragma unroll
        for (int fn = 0; fn < 4; ++fn) {
            int nc = wn * 32 + fn * 8 + lq * 2;
            float bv0 = bn[nc], bv1 = bn[nc + 1];
            float* cc = c[fm][fn];
#pragma unroll
            for (int h = 0; h < 2; ++h) {
                int rloc = rl + h * 8;
                if (rloc < vrows) {
                    int row = row0 + rloc;
                    float v0 = cc[h * 2 + 0] + bv0;
                    float v1 = cc[h * 2 + 1] + bv1;
                    if (FIRST) {
                        v0 = gelu_exact(v0);
                        v1 = gelu_exact(v1);
                        __nv_bfloat16 h0 = __float2bfloat16_rn(v0);
                        __nv_bfloat16 h1 = __float2bfloat16_rn(v1);
                        *reinterpret_cast<uint32_t*>(&g_Hh[(size_t)row * DF + n0 + nc]) = pack_bf16(h0, h1);
                        __nv_bfloat16 l0 = __float2bfloat16_rn(v0 - __bfloat162float(h0));
                        __nv_bfloat16 l1 = __float2bfloat16_rn(v1 - __bfloat162float(h1));
                        *reinterpret_cast<uint32_t*>(&g_Hl[(size_t)row * DF + n0 + nc]) = pack_bf16(l0, l1);
                    } else {
                        *reinterpret_cast<float2*>(&g_Y[(size_t)row * DM + n0 + nc]) = make_float2(v0, v1);
                    }
                }
            }
        }
    }
#endif  // !HAS_TC
}

// ---------------- kernel: weighted combine ----------------
__global__ __launch_bounds__(256) void combine_kernel(float* __restrict__ out) {
    const int tk = blockIdx.x;
    const int d = threadIdx.x * 4;
    int s0 = g_pair_slot[2 * tk], s1 = g_pair_slot[2 * tk + 1];
    float w0 = g_pair_w[2 * tk], w1 = g_pair_w[2 * tk + 1];
    const float4 a = *reinterpret_cast<const float4*>(&g_Y[(size_t)s0 * DM + d]);
    const float4 b = *reinterpret_cast<const float4*>(&g_Y[(size_t)s1 * DM + d]);
    float4 o;
    o.x = w0 * a.x + w1 * b.x;
    o.y = w0 * a.y + w1 * b.y;
    o.z = w0 * a.z + w1 * b.z;
    o.w = w0 * a.w + w1 * b.w;
    *reinterpret_cast<float4*>(&out[(size_t)tk * DM + d]) = o;
}

// ---------------- launch ----------------
extern "C" void kernel_launch(void* const* d_in, const int* in_sizes, int n_in,
                              void* d_out, int out_size) {
    const float* x  = (const float*)d_in[0];
    const float* gw = (const float*)d_in[1];
    const float* w1 = (const float*)d_in[2];
    const float* b1 = (const float*)d_in[3];
    const float* w2 = (const float*)d_in[4];
    const float* b2 = (const float*)d_in[5];
    float* out = (float*)d_out;

    cudaFuncSetAttribute(moe_gemm_tc<true>,  cudaFuncAttributeMaxDynamicSharedMemorySize, SMEM_DYN);
    cudaFuncSetAttribute(moe_gemm_tc<false>, cudaFuncAttributeMaxDynamicSharedMemorySize, SMEM_DYN);

    __nv_bfloat16 *w1h, *w1l, *w2h, *w2l;
    cudaGetSymbolAddress((void**)&w1h, g_w1h);
    cudaGetSymbolAddress((void**)&w1l, g_w1l);
    cudaGetSymbolAddress((void**)&w2h, g_w2h);
    cudaGetSymbolAddress((void**)&w2l, g_w2l);

    gate_kernel<<<T_TOKENS, 256>>>(x, gw);                                   // idx 0
    sortscan_kernel<<<1, 256>>>();                                           // idx 1
    wsplit_kernel<<<dim3(DF / 64, DM / 64, NE), 256>>>(w1, w1h, w1l, DM, DF); // idx 2
    moe_gemm_tc<true><<<dim3(DF / 256, 136), 256, SMEM_DYN>>>(w1h, w1l, b1);  // idx 3 (profile slot)
    moe_gemm_fb<true><<<dim3(DF / 128, 136), 256>>>(w1, b1);                  // idx 4 (no-op on tc build)
    wsplit_kernel<<<dim3(DM / 64, DF / 64, NE), 256>>>(w2, w2h, w2l, DF, DM); // idx 5
    moe_gemm_tc<false><<<dim3(DM / 256, 136), 256, SMEM_DYN>>>(w2h, w2l, b2); // idx 6
    moe_gemm_fb<false><<<dim3(DM / 128, 136), 256>>>(w2, b2);                 // idx 7
    combine_kernel<<<T_TOKENS, 256>>>(out);                                   // idx 8
}

// round 6
// speedup vs baseline: 6.2389x; 1.7997x over previous
#include <cuda_runtime.h>
#include <cuda.h>
#include <cuda_bf16.h>
#include <stdint.h>

#define T_TOKENS 8192
#define DM 1024
#define DF 4096
#define NE 8
#define PAIRS 16384
#define MAXTILES 144

// tcgen05 availability: only in the arch-SPECIFIC device pass (sm_103a / sm_100a).
#if defined(__CUDA_ARCH__) && (defined(__CUDA_ARCH_FEAT_SM103_ALL) || defined(__CUDA_ARCH_FEAT_SM100_ALL) || defined(__CUDA_ARCH_SPECIFIC__))
#define HAS_TC 1
#else
#define HAS_TC 0
#endif

// ---------------- scratch (device globals; no allocations) ----------------
__device__ __align__(128) __nv_bfloat16 g_Ah[(size_t)PAIRS * DM];  // gathered x, slot-ordered, hi
__device__ __align__(128) __nv_bfloat16 g_Al[(size_t)PAIRS * DM];  // lo
__device__ __align__(128) __nv_bfloat16 g_Hh[(size_t)PAIRS * DF];
__device__ __align__(128) __nv_bfloat16 g_Hl[(size_t)PAIRS * DF];
__device__ __align__(128) float         g_Y[(size_t)PAIRS * DM];

// pre-split, pre-transposed weights: [E][N][K] bf16 hi/lo
__device__ __align__(128) __nv_bfloat16 g_w1h[(size_t)NE * DM * DF];
__device__ __align__(128) __nv_bfloat16 g_w1l[(size_t)NE * DM * DF];
__device__ __align__(128) __nv_bfloat16 g_w2h[(size_t)NE * DF * DM];
__device__ __align__(128) __nv_bfloat16 g_w2l[(size_t)NE * DF * DM];

__device__ int   g_pair_e[PAIRS];
__device__ float g_pair_w[PAIRS];
__device__ int   g_pair_slot[PAIRS];
__device__ int   g_rows_token[PAIRS];

__device__ int g_counts[NE];
__device__ int g_off[NE + 1];
__device__ int g_tile_e[MAXTILES];
__device__ int g_tile_r0[MAXTILES];
__device__ int g_tile_valid[MAXTILES];
__device__ int g_num_tiles;

// ---------------- shared helpers ----------------
__device__ __forceinline__ uint32_t smaddr(const void* p) {
    return (uint32_t)__cvta_generic_to_shared(p);
}
__device__ __forceinline__ uint32_t pack_bf16(__nv_bfloat16 a, __nv_bfloat16 b) {
    return (uint32_t)__bfloat16_as_ushort(a) | ((uint32_t)__bfloat16_as_ushort(b) << 16);
}
__device__ __forceinline__ float gelu_exact(float v) {
    return 0.5f * v * (1.0f + erff(v * 0.70710678118654752f));
}

#if HAS_TC
// ---------------- tcgen05-path helpers ----------------
__device__ __forceinline__ uint32_t elect_one() {
    uint32_t pred;
    asm volatile("{\n\t.reg .pred p;\n\telect.sync _|p, 0xFFFFFFFF;\n\tselp.b32 %0, 1, 0, p;\n\t}"
                 : "=r"(pred));
    return pred;
}
__device__ __forceinline__ void mbar_init(uint32_t addr, uint32_t cnt) {
    asm volatile("mbarrier.init.shared.b64 [%0], %1;" :: "r"(addr), "r"(cnt) : "memory");
}
__device__ __forceinline__ void mbar_inval(uint32_t addr) {
    asm volatile("mbarrier.inval.shared.b64 [%0];" :: "r"(addr) : "memory");
}
__device__ __forceinline__ void mbar_expect(uint32_t addr, uint32_t bytes) {
    asm volatile("mbarrier.arrive.expect_tx.shared.b64 _, [%0], %1;"
                 :: "r"(addr), "r"(bytes) : "memory");
}
__device__ __forceinline__ void mbar_wait(uint32_t addr, uint32_t parity) {
    asm volatile(
        "{\n\t.reg .pred P1;\n"
        "WAIT_%=:\n\t"
        "mbarrier.try_wait.parity.acquire.cta.shared::cta.b64 P1, [%0], %1, 0x989680;\n\t"
        "@P1 bra.uni DONE_%=;\n\t"
        "bra.uni WAIT_%=;\n"
        "DONE_%=:\n\t}"
        :: "r"(addr), "r"(parity) : "memory");
}
__device__ __forceinline__ void tma2d(uint32_t dst, const void* tm, int x, int y, uint32_t mbar) {
    asm volatile(
        "cp.async.bulk.tensor.2d.shared::cta.global.tile.mbarrier::complete_tx::bytes "
        "[%0], [%1, {%2, %3}], [%4];"
        :: "r"(dst), "l"(tm), "r"(x), "r"(y), "r"(mbar) : "memory");
}
__device__ __forceinline__ void tma3d(uint32_t dst, const void* tm, int x, int y, int z, uint32_t mbar) {
    asm volatile(
        "cp.async.bulk.tensor.3d.shared::cta.global.tile.mbarrier::complete_tx::bytes "
        "[%0], [%1, {%2, %3, %4}], [%5];"
        :: "r"(dst), "l"(tm), "r"(x), "r"(y), "r"(z), "r"(mbar) : "memory");
}
__device__ __forceinline__ void tc_mma_f16_ss(uint32_t d, uint64_t a, uint64_t b,
                                              uint32_t idesc, uint32_t en) {
    asm volatile(
        "{\n\t.reg .pred p;\n\tsetp.ne.u32 p, %5, 0;\n\t"
        "tcgen05.mma.cta_group::1.kind::f16 [%0], %1, %2, %3, {%4, %4, %4, %4}, p;\n\t}"
        :: "r"(d), "l"(a), "l"(b), "r"(idesc), "r"(0u), "r"(en) : "memory");
}
__device__ __forceinline__ void tc_commit(uint32_t mbar) {
    asm volatile("tcgen05.commit.cta_group::1.mbarrier::arrive::one.shared::cluster.b64 [%0];"
                 :: "r"(mbar) : "memory");
}
__device__ __forceinline__ void tc_alloc(uint32_t smem_slot, uint32_t ncols) {
    asm volatile("tcgen05.alloc.cta_group::1.sync.aligned.shared::cta.b32 [%0], %1;"
                 :: "r"(smem_slot), "r"(ncols) : "memory");
}
__device__ __forceinline__ void tc_dealloc(uint32_t tmem, uint32_t ncols) {
    asm volatile("tcgen05.dealloc.cta_group::1.sync.aligned.b32 %0, %1;" :: "r"(tmem), "r"(ncols));
}
__device__ __forceinline__ void tc_relinq() {
    asm volatile("tcgen05.relinquish_alloc_permit.cta_group::1.sync.aligned;");
}
__device__ __forceinline__ void tc_fence_after() {
    asm volatile("tcgen05.fence::after_thread_sync;" ::: "memory");
}
__device__ __forceinline__ void tc_wait_ld() {
    asm volatile("tcgen05.wait::ld.sync.aligned;" ::: "memory");
}
__device__ __forceinline__ void tc_ld_x32(uint32_t* r, uint32_t addr) {
    asm volatile(
        "tcgen05.ld.sync.aligned.32x32b.x32.b32 "
        "{%0, %1, %2, %3, %4, %5, %6, %7, %8, %9, %10, %11, %12, %13, %14, %15, "
        " %16, %17, %18, %19, %20, %21, %22, %23, %24, %25, %26, %27, %28, %29, %30, %31}, [%32];"
        : "=r"(r[0]), "=r"(r[1]), "=r"(r[2]), "=r"(r[3]), "=r"(r[4]), "=r"(r[5]), "=r"(r[6]), "=r"(r[7]),
          "=r"(r[8]), "=r"(r[9]), "=r"(r[10]), "=r"(r[11]), "=r"(r[12]), "=r"(r[13]), "=r"(r[14]), "=r"(r[15]),
          "=r"(r[16]), "=r"(r[17]), "=r"(r[18]), "=r"(r[19]), "=r"(r[20]), "=r"(r[21]), "=r"(r[22]), "=r"(r[23]),
          "=r"(r[24]), "=r"(r[25]), "=r"(r[26]), "=r"(r[27]), "=r"(r[28]), "=r"(r[29]), "=r"(r[30]), "=r"(r[31])
        : "r"(addr));
}
// SW128 K-major descriptor base (LBO=1, SBO=64, version=1, layout SW128)
__device__ __forceinline__ uint64_t mk_desc(uint32_t addr) {
    const uint64_t DBASE = (2ULL << 61) | (1ULL << 46) | (64ULL << 32) | (1ULL << 16);
    return DBASE | (uint64_t)((addr >> 4) & 0x3FFF);
}
#endif  // HAS_TC

#if !HAS_TC
// ---------------- fallback-path helpers (mma.sync) ----------------
__device__ __forceinline__ void ldsm4(uint32_t* r, uint32_t addr) {
    asm volatile("ldmatrix.sync.aligned.m8n8.x4.shared.b16 {%0,%1,%2,%3}, [%4];\n"
                 : "=r"(r[0]), "=r"(r[1]), "=r"(r[2]), "=r"(r[3]) : "r"(addr));
}
__device__ __forceinline__ void ldsm4t(uint32_t* r, uint32_t addr) {
    asm volatile("ldmatrix.sync.aligned.m8n8.x4.trans.shared.b16 {%0,%1,%2,%3}, [%4];\n"
                 : "=r"(r[0]), "=r"(r[1]), "=r"(r[2]), "=r"(r[3]) : "r"(addr));
}
__device__ __forceinline__ void mma16816(float* c, const uint32_t* a, const uint32_t* b) {
    asm volatile(
        "mma.sync.aligned.m16n8k16.row.col.f32.bf16.bf16.f32 "
        "{%0,%1,%2,%3}, {%4,%5,%6,%7}, {%8,%9}, {%0,%1,%2,%3};\n"
        : "+f"(c[0]), "+f"(c[1]), "+f"(c[2]), "+f"(c[3])
        : "r"(a[0]), "r"(a[1]), "r"(a[2]), "r"(a[3]), "r"(b[0]), "r"(b[1]));
}
#endif  // !HAS_TC

// ---------------- kernel: gating (routing only) ----------------
__global__ __launch_bounds__(256) void gate_kernel(const float* __restrict__ x,
                                                   const float* __restrict__ gw) {
    const int tk = blockIdx.x;
    const int tid = threadIdx.x;
    const float* xr = x + (size_t)tk * DM;

    float p[NE];
#pragma unroll
    for (int e = 0; e < NE; ++e) p[e] = 0.f;
#pragma unroll
    for (int j = 0; j < 4; ++j) {
        int i = j * 256 + tid;
        float v = xr[i];
#pragma unroll
        for (int e = 0; e < NE; ++e) p[e] += v * gw[e * DM + i];
    }
#pragma unroll
    for (int e = 0; e < NE; ++e)
#pragma unroll
        for (int o = 16; o > 0; o >>= 1) p[e] += __shfl_xor_sync(0xffffffffu, p[e], o);

    __shared__ float sRed[8][NE];
    int lane = tid & 31, w = tid >> 5;
    if (lane == 0) {
#pragma unroll
        for (int e = 0; e < NE; ++e) sRed[w][e] = p[e];
    }
    __syncthreads();
    if (tid == 0) {
        float lg[NE];
#pragma unroll
        for (int e = 0; e < NE; ++e) {
            float s = 0.f;
#pragma unroll
            for (int ww = 0; ww < 8; ++ww) s += sRed[ww][e];
            lg[e] = s;
        }
        float m = lg[0];
#pragma unroll
        for (int e = 1; e < NE; ++e) m = fmaxf(m, lg[e]);
        float ex[NE], S = 0.f;
#pragma unroll
        for (int e = 0; e < NE; ++e) { ex[e] = expf(lg[e] - m); S += ex[e]; }
        int i0 = 0;
#pragma unroll
        for (int e = 1; e < NE; ++e) if (ex[e] > ex[i0]) i0 = e;
        int i1 = (i0 == 0) ? 1 : 0;
#pragma unroll
        for (int e = 0; e < NE; ++e) if (e != i0 && ex[e] > ex[i1]) i1 = e;
        float p0 = ex[i0] / S, p1 = ex[i1] / S;
        float den = p0 + p1 + 1e-9f;
        g_pair_e[2 * tk] = i0;     g_pair_w[2 * tk] = p0 / den;
        g_pair_e[2 * tk + 1] = i1; g_pair_w[2 * tk + 1] = p1 / den;
    }
}

// ---------------- kernel: counting sort (counts + scan + tiles + scatter) ----------------
__global__ __launch_bounds__(256) void sortscan_kernel() {
    __shared__ uint16_t loc[256][NE];
    __shared__ int s_cnt[NE];
    __shared__ int s_off[NE];
    const int t = threadIdx.x;
    const int p0 = t * 64;

    int lc[NE];
#pragma unroll
    for (int e = 0; e < NE; ++e) lc[e] = 0;
    for (int i = 0; i < 64; ++i) lc[g_pair_e[p0 + i]]++;
#pragma unroll
    for (int e = 0; e < NE; ++e) loc[t][e] = (uint16_t)lc[e];
    __syncthreads();

    if (t < NE) {
        int run = 0;
        for (int i = 0; i < 256; ++i) {
            int c = loc[i][t];
            loc[i][t] = (uint16_t)run;
            run += c;
        }
        s_cnt[t] = run;
        g_counts[t] = run;
    }
    __syncthreads();

    if (t == 0) {
        int off = 0, nt = 0;
        for (int e = 0; e < NE; ++e) {
            g_off[e] = off;
            s_off[e] = off;
            int c = s_cnt[e];
            int tiles = (c + 127) >> 7;
            for (int i = 0; i < tiles; ++i) {
                g_tile_e[nt] = e;
                g_tile_r0[nt] = off + i * 128;
                int v = c - i * 128;
                g_tile_valid[nt] = v > 128 ? 128 : v;
                ++nt;
            }
            off += c;
        }
        g_off[NE] = off;
        g_num_tiles = nt;
    }
    __syncthreads();

    int run[NE];
#pragma unroll
    for (int e = 0; e < NE; ++e) run[e] = s_off[e] + (int)loc[t][e];
    for (int i = 0; i < 64; ++i) {
        int p = p0 + i;
        int e = g_pair_e[p];
        int slot = run[e]++;
        g_pair_slot[p] = slot;
        g_rows_token[slot] = p >> 1;
    }
}

// ---------------- kernel: prep = A-gather (z==16) + weight split/transpose (z<16) ----------------
__global__ __launch_bounds__(256) void prep_kernel(const float* __restrict__ x,
                                                   const float* __restrict__ w1,
                                                   const float* __restrict__ w2) {
    const int z = blockIdx.z;
    const int t = threadIdx.x;

    if (z == 16) {
        // gather: 1024 blocks (y*64+x), 16 slot rows each; split x rows to hi/lo bf16
        const int b = blockIdx.y * 64 + blockIdx.x;
        for (int rr = 0; rr < 16; ++rr) {
            const int slot = b * 16 + rr;
            const int tok = g_rows_token[slot];
            const float4 v = reinterpret_cast<const float4*>(x + (size_t)tok * DM)[t];
            __nv_bfloat16 h0 = __float2bfloat16_rn(v.x), h1 = __float2bfloat16_rn(v.y);
            __nv_bfloat16 h2 = __float2bfloat16_rn(v.z), h3 = __float2bfloat16_rn(v.w);
            __nv_bfloat16 l0 = __float2bfloat16_rn(v.x - __bfloat162float(h0));
            __nv_bfloat16 l1 = __float2bfloat16_rn(v.y - __bfloat162float(h1));
            __nv_bfloat16 l2 = __float2bfloat16_rn(v.z - __bfloat162float(h2));
            __nv_bfloat16 l3 = __float2bfloat16_rn(v.w - __bfloat162float(h3));
            reinterpret_cast<uint2*>(g_Ah + (size_t)slot * DM)[t] =
                make_uint2(pack_bf16(h0, h1), pack_bf16(h2, h3));
            reinterpret_cast<uint2*>(g_Al + (size_t)slot * DM)[t] =
                make_uint2(pack_bf16(l0, l1), pack_bf16(l2, l3));
        }
        return;
    }

#if HAS_TC
    // wsplit: in W[e][k][n] fp32 -> out Wh/Wl[e][n][k] bf16 (k contiguous)
    __shared__ float tile[64][65];
    const int layer = z >> 3;
    const int e = z & 7;
    const int K = layer ? DF : DM;
    const int N = layer ? DM : DF;
    const int K0 = (layer ? blockIdx.x : blockIdx.y) * 64;
    const int N0 = (layer ? blockIdx.y : blockIdx.x) * 64;
    const float* W = layer ? w2 : w1;
    __nv_bfloat16* Wh = layer ? g_w2h : g_w1h;
    __nv_bfloat16* Wl = layer ? g_w2l : g_w1l;

    const float* src = W + ((size_t)e * K + K0) * N + N0;
    const int r = t >> 4, c4 = (t & 15) * 4;
#pragma unroll
    for (int j = 0; j < 4; ++j) {
        int rr = r + j * 16;
        const float4 v = *reinterpret_cast<const float4*>(src + (size_t)rr * N + c4);
        tile[rr][c4 + 0] = v.x; tile[rr][c4 + 1] = v.y;
        tile[rr][c4 + 2] = v.z; tile[rr][c4 + 3] = v.w;
    }
    __syncthreads();
#pragma unroll
    for (int j = 0; j < 4; ++j) {
        int nn = r + j * 16;
        float v0 = tile[c4 + 0][nn], v1 = tile[c4 + 1][nn];
        float v2 = tile[c4 + 2][nn], v3 = tile[c4 + 3][nn];
        __nv_bfloat16 h0 = __float2bfloat16_rn(v0), h1 = __float2bfloat16_rn(v1);
        __nv_bfloat16 h2 = __float2bfloat16_rn(v2), h3 = __float2bfloat16_rn(v3);
        __nv_bfloat16 l0 = __float2bfloat16_rn(v0 - __bfloat162float(h0));
        __nv_bfloat16 l1 = __float2bfloat16_rn(v1 - __bfloat162float(h1));
        __nv_bfloat16 l2 = __float2bfloat16_rn(v2 - __bfloat162float(h2));
        __nv_bfloat16 l3 = __float2bfloat16_rn(v3 - __bfloat162float(h3));
        size_t out = ((size_t)e * N + N0 + nn) * K + K0 + c4;
        *reinterpret_cast<uint2*>(Wh + out) = make_uint2(pack_bf16(h0, h1), pack_bf16(h2, h3));
        *reinterpret_cast<uint2*>(Wl + out) = make_uint2(pack_bf16(l0, l1), pack_bf16(l2, l3));
    }
#endif
}

// ---------------- tcgen05 GEMM (full TMA, single orchestrator) ----------------
// BM=128, BN=256, K-stage=64. 2 stages x 96KB. SS mode cg1, 3-pass hi/lo bf16.
#define BUF_STRIDE 98304
#define OFF_AL 16384
#define OFF_BH 32768
#define OFF_BL 65536
#define OFF_TMEM 196608
#define OFF_MBAR 196624
#define SMEM_DYN 198656
#define STAGE_BYTES 98304u

#define GEMM_IDESC ((1u << 4) | (1u << 7) | (1u << 10) | ((256u / 8) << 17) | ((128u / 16) << 24))

template <bool FIRST>
__global__ __launch_bounds__(256) void moe_gemm_tc(const __grid_constant__ CUtensorMap tmAh,
                                                   const __grid_constant__ CUtensorMap tmAl,
                                                   const __grid_constant__ CUtensorMap tmBh,
                                                   const __grid_constant__ CUtensorMap tmBl,
                                                   const float* __restrict__ bias) {
#if HAS_TC
    constexpr int KTOT = FIRST ? DM : DF;
    constexpr int NTOT = FIRST ? DF : DM;
    constexpr int NC = KTOT / 64;

    const int tileIdx = blockIdx.y;
    if (tileIdx >= g_num_tiles) return;
    const int e = g_tile_e[tileIdx];
    const int row0 = g_tile_r0[tileIdx];
    const int vrows = g_tile_valid[tileIdx];
    const int n0 = blockIdx.x * 256;

    extern __shared__ char dyn[];
    const uint32_t raw = smaddr(dyn);
    const uint32_t sbase = (raw + 1023u) & ~1023u;
    const int t = threadIdx.x;
    const int w = t >> 5, lane = t & 31;

    if (t == 0) {
#pragma unroll
        for (int s = 0; s < 4; ++s) mbar_init(sbase + OFF_MBAR + s * 8, 1);
    }
    if (w == 0) {
        tc_alloc(sbase + OFF_TMEM, 256);
        tc_relinq();
    }
    __syncthreads();

    uint32_t tmem;
    asm volatile("ld.shared.b32 %0, [%1];" : "=r"(tmem) : "r"(sbase + OFF_TMEM));

    uint64_t dAh[2], dAl[2], dBh[2], dBl[2];
#pragma unroll
    for (int s = 0; s < 2; ++s) {
        uint32_t b = sbase + s * BUF_STRIDE;
        dAh[s] = mk_desc(b);
        dAl[s] = mk_desc(b + OFF_AL);
        dBh[s] = mk_desc(b + OFF_BH);
        dBl[s] = mk_desc(b + OFF_BL);
    }

    if (w == 0 && elect_one()) {
        const uint32_t mbF = sbase + OFF_MBAR;        // full[0..1]
        const uint32_t mbM = sbase + OFF_MBAR + 16;   // mma[0..1]

        auto issue = [&](int i, int s) {
            const uint32_t bb = sbase + (uint32_t)s * BUF_STRIDE;
            const int k0 = i * 64;
            mbar_expect(mbF + s * 8, STAGE_BYTES);
            tma2d(bb,          (const void*)&tmAh, k0, row0, mbF + s * 8);
            tma2d(bb + OFF_AL, (const void*)&tmAl, k0, row0, mbF + s * 8);
            tma3d(bb + OFF_BH, (const void*)&tmBh, k0, n0, e, mbF + s * 8);
            tma3d(bb + OFF_BL, (const void*)&tmBl, k0, n0, e, mbF + s * 8);
        };

        issue(0, 0);
        issue(1, 1);

        uint32_t pF[2] = {0, 0}, pM[2] = {0, 0};
#pragma unroll 1
        for (int i = 0; i < NC; ++i) {
            const int s = i & 1;
            mbar_wait(mbF + s * 8, pF[s]); pF[s] ^= 1;
#pragma unroll
            for (int ks = 0; ks < 4; ++ks) {
                const uint64_t oa = (uint64_t)(ks * 2);
                const uint32_t en0 = (i == 0 && ks == 0) ? 0u : 1u;
                tc_mma_f16_ss(tmem, dAh[s] + oa, dBh[s] + oa, GEMM_IDESC, en0);
                tc_mma_f16_ss(tmem, dAh[s] + oa, dBl[s] + oa, GEMM_IDESC, 1u);
                tc_mma_f16_ss(tmem, dAl[s] + oa, dBh[s] + oa, GEMM_IDESC, 1u);
            }
            tc_commit(mbM + s * 8);
            if (i + 2 < NC) {
                mbar_wait(mbM + s * 8, pM[s]); pM[s] ^= 1;
                issue(i + 2, s);
            }
        }
        // drain last two MMA commits
        {
            const int s2 = (NC - 2) & 1;
            mbar_wait(mbM + s2 * 8, pM[s2]); pM[s2] ^= 1;
            const int s1 = (NC - 1) & 1;
            mbar_wait(mbM + s1 * 8, pM[s1]);
        }
    }
    __syncthreads();
    tc_fence_after();

    // ---------------- epilogue ----------------
    const int rloc = (w & 3) * 32 + lane;
    const int cbase = (w >> 2) * 128;
    const bool valid = rloc < vrows;
    const int rowg = row0 + rloc;
    const float* bn = bias + (size_t)e * NTOT + n0 + cbase;

#pragma unroll
    for (int j = 0; j < 4; ++j) {
        uint32_t dr[32];
        tc_ld_x32(dr, tmem + cbase + j * 32);
        tc_wait_ld();
        if (valid) {
            int nb = cbase + j * 32;
            if (FIRST) {
                __nv_bfloat16* oH = g_Hh + (size_t)rowg * DF + n0 + nb;
                __nv_bfloat16* oL = g_Hl + (size_t)rowg * DF + n0 + nb;
#pragma unroll
                for (int c = 0; c < 32; c += 2) {
                    float v0 = gelu_exact(__uint_as_float(dr[c]) + bn[j * 32 + c]);
                    float v1 = gelu_exact(__uint_as_float(dr[c + 1]) + bn[j * 32 + c + 1]);
                    __nv_bfloat16 h0 = __float2bfloat16_rn(v0);
                    __nv_bfloat16 h1 = __float2bfloat16_rn(v1);
                    *reinterpret_cast<uint32_t*>(oH + c) = pack_bf16(h0, h1);
                    __nv_bfloat16 l0 = __float2bfloat16_rn(v0 - __bfloat162float(h0));
                    __nv_bfloat16 l1 = __float2bfloat16_rn(v1 - __bfloat162float(h1));
                    *reinterpret_cast<uint32_t*>(oL + c) = pack_bf16(l0, l1);
                }
            } else {
                float* oY = g_Y + (size_t)rowg * DM + n0 + nb;
#pragma unroll
                for (int c = 0; c < 32; c += 2) {
                    float v0 = __uint_as_float(dr[c]) + bn[j * 32 + c];
                    float v1 = __uint_as_float(dr[c + 1]) + bn[j * 32 + c + 1];
                    *reinterpret_cast<float2*>(oY + c) = make_float2(v0, v1);
                }
            }
        }
    }

    __syncthreads();
    if (t == 0) {
#pragma unroll
        for (int s = 0; s < 4; ++s) mbar_inval(sbase + OFF_MBAR + s * 8);
    }
    if (w == 0) tc_dealloc(tmem, 256);
#endif  // HAS_TC
}

// ---------------- fallback GEMM (mma.sync, only when tcgen05 absent) ----------------
template <bool FIRST>
__global__ __launch_bounds__(256) void moe_gemm_fb(const float* __restrict__ W,
                                                   const float* __restrict__ bias) {
#if !HAS_TC
    constexpr int KTOT = FIRST ? DM : DF;
    constexpr int LDW  = FIRST ? DF : DM;
    const int tileIdx = blockIdx.y;
    if (tileIdx >= g_num_tiles) return;
    const int e = g_tile_e[tileIdx];
    const int row0 = g_tile_r0[tileIdx];
    const int vrows = g_tile_valid[tileIdx];
    const int n0 = blockIdx.x * 128;
    const float* Wn = W + (size_t)e * KTOT * LDW + n0;
    const float* bn = bias + (size_t)e * LDW + n0;

    __shared__ __align__(16) __nv_bfloat16 sAh[128 * 40];
    __shared__ __align__(16) __nv_bfloat16 sAl[128 * 40];
    __shared__ __align__(16) __nv_bfloat16 sBh[32 * 136];
    __shared__ __align__(16) __nv_bfloat16 sBl[32 * 136];

    const int t = threadIdx.x;
    float c[4][4][4];
#pragma unroll
    for (int a = 0; a < 4; ++a)
#pragma unroll
        for (int b = 0; b < 4; ++b)
#pragma unroll
            for (int q = 0; q < 4; ++q) c[a][b][q] = 0.f;

    const int lane = t & 31, warp = t >> 5;
    const int wm = warp >> 2, wn = warp & 3;
    const int m0 = wm * 64;
    const int sub = t & 15, rgrp = t >> 4;

    for (int k0 = 0; k0 < KTOT; k0 += 32) {
        __syncthreads();
#pragma unroll
        for (int rr = 0; rr < 8; ++rr) {
            int r = rr * 16 + rgrp;
            int rg = row0 + r; if (rg > PAIRS - 1) rg = PAIRS - 1;
            const uint32_t* ph = reinterpret_cast<const uint32_t*>(
                (FIRST ? g_Ah : g_Hh) + (size_t)rg * KTOT + k0);
            const uint32_t* pl = reinterpret_cast<const uint32_t*>(
                (FIRST ? g_Al : g_Hl) + (size_t)rg * KTOT + k0);
            *reinterpret_cast<uint32_t*>(&sAh[r * 40 + sub * 2]) = ph[sub];
            *reinterpret_cast<uint32_t*>(&sAl[r * 40 + sub * 2]) = pl[sub];
        }
#pragma unroll
        for (int i = 0; i < 4; ++i) {
            int lin = (i * 256 + t) * 4;
            int kr = lin >> 7;
            int nc = lin & 127;
            const float4 v = *reinterpret_cast<const float4*>(Wn + (size_t)(k0 + kr) * LDW + nc);
            __nv_bfloat16 h0 = __float2bfloat16_rn(v.x);
            __nv_bfloat16 h1 = __float2bfloat16_rn(v.y);
            __nv_bfloat16 h2 = __float2bfloat16_rn(v.z);
            __nv_bfloat16 h3 = __float2bfloat16_rn(v.w);
            __nv_bfloat16 l0 = __float2bfloat16_rn(v.x - __bfloat162float(h0));
            __nv_bfloat16 l1 = __float2bfloat16_rn(v.y - __bfloat162float(h1));
            __nv_bfloat16 l2 = __float2bfloat16_rn(v.z - __bfloat162float(h2));
            __nv_bfloat16 l3 = __float2bfloat16_rn(v.w - __bfloat162float(h3));
            *reinterpret_cast<uint2*>(&sBh[kr * 136 + nc]) = make_uint2(pack_bf16(h0, h1), pack_bf16(h2, h3));
            *reinterpret_cast<uint2*>(&sBl[kr * 136 + nc]) = make_uint2(pack_bf16(l0, l1), pack_bf16(l2, l3));
        }
        __syncthreads();

#pragma unroll
        for (int ks = 0; ks < 2; ++ks) {
            uint32_t ah[4][4], al[4][4], bh[4][2], bl[4][2];
            {
                int ar = lane & 15;
                int acol = ks * 16 + (lane >> 4) * 8;
#pragma unroll
                for (int fm = 0; fm < 4; ++fm) {
                    ldsm4(ah[fm], smaddr(&sAh[(m0 + fm * 16 + ar) * 40 + acol]));
                    ldsm4(al[fm], smaddr(&sAl[(m0 + fm * 16 + ar) * 40 + acol]));
                }
                int brow = ks * 16 + (lane & 15);
                int bcol = wn * 32 + (lane >> 4) * 8;
#pragma unroll
                for (int hb = 0; hb < 2; ++hb) {
                    uint32_t r[4];
                    ldsm4t(r, smaddr(&sBh[brow * 136 + bcol + hb * 16]));
                    bh[2 * hb][0] = r[0]; bh[2 * hb][1] = r[1];
                    bh[2 * hb + 1][0] = r[2]; bh[2 * hb + 1][1] = r[3];
                    ldsm4t(r, smaddr(&sBl[brow * 136 + bcol + hb * 16]));
                    bl[2 * hb][0] = r[0]; bl[2 * hb][1] = r[1];
                    bl[2 * hb + 1][0] = r[2]; bl[2 * hb + 1][1] = r[3];
                }
            }
#pragma unroll
            for (int fm = 0; fm < 4; ++fm)
#pragma unroll
                for (int fn = 0; fn < 4; ++fn) {
                    mma16816(c[fm][fn], ah[fm], bh[fn]);
                    mma16816(c[fm][fn], ah[fm], bl[fn]);
                    mma16816(c[fm][fn], al[fm], bh[fn]);
                }
        }
    }

    const int lgrp = lane >> 2, lq = lane & 3;
#pragma unroll
    for (int fm = 0; fm < 4; ++fm) {
        int rl = m0 + fm * 16 + lgrp;
#pragma unroll
        for (int fn = 0; fn < 4; ++fn) {
            int nc = wn * 32 + fn * 8 + lq * 2;
            float bv0 = bn[nc], bv1 = bn[nc + 1];
            float* cc = c[fm][fn];
#pragma unroll
            for (int h = 0; h < 2; ++h) {
                int rloc = rl + h * 8;
                if (rloc < vrows) {
                    int row = row0 + rloc;
                    float v0 = cc[h * 2 + 0] + bv0;
                    float v1 = cc[h * 2 + 1] + bv1;
                    if (FIRST) {
                        v0 = gelu_exact(v0);
                        v1 = gelu_exact(v1);
                        __nv_bfloat16 h0 = __float2bfloat16_rn(v0);
                        __nv_bfloat16 h1 = __float2bfloat16_rn(v1);
                        *reinterpret_cast<uint32_t*>(&g_Hh[(size_t)row * DF + n0 + nc]) = pack_bf16(h0, h1);
                        __nv_bfloat16 l0 = __float2bfloat16_rn(v0 - __bfloat162float(h0));
                        __nv_bfloat16 l1 = __float2bfloat16_rn(v1 - __bfloat162float(h1));
                        *reinterpret_cast<uint32_t*>(&g_Hl[(size_t)row * DF + n0 + nc]) = pack_bf16(l0, l1);
                    } else {
                        *reinterpret_cast<float2*>(&g_Y[(size_t)row * DM + n0 + nc]) = make_float2(v0, v1);
                    }
                }
            }
        }
    }
#endif  // !HAS_TC
}

// ---------------- kernel: weighted combine ----------------
__global__ __launch_bounds__(256) void combine_kernel(float* __restrict__ out) {
    const int tk = blockIdx.x;
    const int d = threadIdx.x * 4;
    int s0 = g_pair_slot[2 * tk], s1 = g_pair_slot[2 * tk + 1];
    float w0 = g_pair_w[2 * tk], w1 = g_pair_w[2 * tk + 1];
    const float4 a = *reinterpret_cast<const float4*>(&g_Y[(size_t)s0 * DM + d]);
    const float4 b = *reinterpret_cast<const float4*>(&g_Y[(size_t)s1 * DM + d]);
    float4 o;
    o.x = w0 * a.x + w1 * b.x;
    o.y = w0 * a.y + w1 * b.y;
    o.z = w0 * a.z + w1 * b.z;
    o.w = w0 * a.w + w1 * b.w;
    *reinterpret_cast<float4*>(&out[(size_t)tk * DM + d]) = o;
}

// ---------------- host: tensor map construction ----------------
typedef CUresult (*TmEncodeFn)(CUtensorMap*, CUtensorMapDataType, cuuint32_t, void*,
                               const cuuint64_t*, const cuuint64_t*, const cuuint32_t*,
                               const cuuint32_t*, CUtensorMapInterleave, CUtensorMapSwizzle,
                               CUtensorMapL2promotion, CUtensorMapFloatOOBfill);

static void tm2d(TmEncodeFn enc, CUtensorMap* tm, void* base, unsigned long long K,
                 unsigned long long R) {
    cuuint64_t dims[2] = {K, R};
    cuuint64_t st[1] = {K * 2};
    cuuint32_t box[2] = {64, 128};
    cuuint32_t es[2] = {1, 1};
    enc(tm, CU_TENSOR_MAP_DATA_TYPE_BFLOAT16, 2, base, dims, st, box, es,
        CU_TENSOR_MAP_INTERLEAVE_NONE, CU_TENSOR_MAP_SWIZZLE_128B,
        CU_TENSOR_MAP_L2_PROMOTION_L2_128B, CU_TENSOR_MAP_FLOAT_OOB_FILL_NONE);
}
static void tm3d(TmEncodeFn enc, CUtensorMap* tm, void* base, unsigned long long K,
                 unsigned long long N) {
    cuuint64_t dims[3] = {K, N, NE};
    cuuint64_t st[2] = {K * 2, N * K * 2};
    cuuint32_t box[3] = {64, 256, 1};
    cuuint32_t es[3] = {1, 1, 1};
    enc(tm, CU_TENSOR_MAP_DATA_TYPE_BFLOAT16, 3, base, dims, st, box, es,
        CU_TENSOR_MAP_INTERLEAVE_NONE, CU_TENSOR_MAP_SWIZZLE_128B,
        CU_TENSOR_MAP_L2_PROMOTION_L2_128B, CU_TENSOR_MAP_FLOAT_OOB_FILL_NONE);
}

// ---------------- launch ----------------
extern "C" void kernel_launch(void* const* d_in, const int* in_sizes, int n_in,
                              void* d_out, int out_size) {
    const float* x  = (const float*)d_in[0];
    const float* gw = (const float*)d_in[1];
    const float* w1 = (const float*)d_in[2];
    const float* b1 = (const float*)d_in[3];
    const float* w2 = (const float*)d_in[4];
    const float* b2 = (const float*)d_in[5];
    float* out = (float*)d_out;

    cudaFuncSetAttribute(moe_gemm_tc<true>,  cudaFuncAttributeMaxDynamicSharedMemorySize, SMEM_DYN);
    cudaFuncSetAttribute(moe_gemm_tc<false>, cudaFuncAttributeMaxDynamicSharedMemorySize, SMEM_DYN);

    void *pAh, *pAl, *pHh, *pHl, *pW1h, *pW1l, *pW2h, *pW2l;
    cudaGetSymbolAddress(&pAh, g_Ah);
    cudaGetSymbolAddress(&pAl, g_Al);
    cudaGetSymbolAddress(&pHh, g_Hh);
    cudaGetSymbolAddress(&pHl, g_Hl);
    cudaGetSymbolAddress(&pW1h, g_w1h);
    cudaGetSymbolAddress(&pW1l, g_w1l);
    cudaGetSymbolAddress(&pW2h, g_w2h);
    cudaGetSymbolAddress(&pW2l, g_w2l);

    void* sym = nullptr;
    cudaDriverEntryPointQueryResult qr;
    cudaGetDriverEntryPoint("cuTensorMapEncodeTiled", &sym, cudaEnableDefault, &qr);
    TmEncodeFn enc = (TmEncodeFn)sym;

    CUtensorMap tAh, tAl, tB1h, tB1l, tHh, tHl, tB2h, tB2l;
    if (enc) {
        tm2d(enc, &tAh, pAh, DM, PAIRS);
        tm2d(enc, &tAl, pAl, DM, PAIRS);
        tm3d(enc, &tB1h, pW1h, DM, DF);
        tm3d(enc, &tB1l, pW1l, DM, DF);
        tm2d(enc, &tHh, pHh, DF, PAIRS);
        tm2d(enc, &tHl, pHl, DF, PAIRS);
        tm3d(enc, &tB2h, pW2h, DF, DM);
        tm3d(enc, &tB2l, pW2l, DF, DM);
    }

    gate_kernel<<<T_TOKENS, 256>>>(x, gw);                                     // idx 0
    sortscan_kernel<<<1, 256>>>();                                             // idx 1
    prep_kernel<<<dim3(64, 16, 17), 256>>>(x, w1, w2);                         // idx 2
    moe_gemm_tc<true><<<dim3(DF / 256, 136), 256, SMEM_DYN>>>(tAh, tAl, tB1h, tB1l, b1);   // idx 3
    moe_gemm_fb<true><<<dim3(DF / 128, 136), 256>>>(w1, b1);                   // idx 4 (no-op on tc build)
    moe_gemm_tc<false><<<dim3(DM / 256, 136), 256, SMEM_DYN>>>(tHh, tHl, tB2h, tB2l, b2);  // idx 5
    moe_gemm_fb<false><<<dim3(DM / 128, 136), 256>>>(w2, b2);                  // idx 6
    combine_kernel<<<T_TOKENS, 256>>>(out);                                    // idx 7
}